// round 10
// baseline (speedup 1.0000x reference)
#include <cuda_runtime.h>
#include <cstdint>

#define NN 20000
#define EE 320000
#define FF 128
#define D0 256
#define D1 512
#define HH 2
#define CC 256
#define GG 128
#define NC 10

// ---------------- scratch (device globals; zero-initialized at load) ----------------
__device__ float g_h1[NN * D0];
__device__ float g_h2[NN * D0];
__device__ float g_xw[NN * D1];
__device__ float g_h3[NN * D1];
__device__ float g_h4[NN * D1];
__device__ float g_wt0[FF * D0];
__device__ float g_wt1[D0 * D0];
__device__ float g_wt2[D0 * D1];
__device__ float g_wt3[D1 * D1];
__device__ float g_ls0[NN * HH], g_ld0[NN * HH];
__device__ float g_ls1[NN * HH], g_ld1[NN * HH];
__device__ int   g_deg[NN];      // invariant: all-zero at kernel_launch entry
__device__ int   g_off[NN + 1];
__device__ int   g_cur[NN];
__device__ int   g_csr[EE];
__device__ int   g_bsum[64];
__device__ int   g_goff[GG + 1];
__device__ float g_sc1[D0], g_sh1[D0], g_sc2[D0], g_sh2[D0];

// ---------------- small helpers ----------------
__device__ __forceinline__ float rtf32(float x) {
    uint32_t u;
    asm("cvt.rna.tf32.f32 %0, %1;" : "=r"(u) : "f"(x));
    return __uint_as_float(u);
}
__device__ __forceinline__ uint32_t smem_u32(const void* p) {
    uint32_t a;
    asm("{ .reg .u64 t; cvta.to.shared.u64 t, %1; cvt.u32.u64 %0, t; }" : "=r"(a) : "l"(p));
    return a;
}
__device__ __forceinline__ void cpa16(uint32_t dst, const void* src, int sz) {
    asm volatile("cp.async.ca.shared.global [%0], [%1], 16, %2;"
                 :: "r"(dst), "l"(src), "r"(sz));
}
__device__ __forceinline__ void cp_commit() {
    asm volatile("cp.async.commit_group;");
}
template <int N>
__device__ __forceinline__ void cp_wait() {
    asm volatile("cp.async.wait_group %0;" :: "n"(N));
}
__device__ __forceinline__ void mma_tf32(float* d, const float* a, const float* b) {
    asm volatile(
        "mma.sync.aligned.m16n8k8.row.col.f32.tf32.tf32.f32 "
        "{%0,%1,%2,%3}, {%4,%5,%6,%7}, {%8,%9}, {%0,%1,%2,%3};"
        : "+f"(d[0]), "+f"(d[1]), "+f"(d[2]), "+f"(d[3])
        : "r"(__float_as_uint(a[0])), "r"(__float_as_uint(a[1])),
          "r"(__float_as_uint(a[2])), "r"(__float_as_uint(a[3])),
          "r"(__float_as_uint(b[0])), "r"(__float_as_uint(b[1])));
}

// ---------------- fused prepass: hist + zeros + graph bounds + BN fold + transposes ----------------
#define NB_ED ((EE + 255) / 256)        // 1250
#define NB_TR 480

__global__ void fused_pre(const int* __restrict__ batch,
                          const int* __restrict__ ei, const int* __restrict__ ew,
                          const float* lb1, const float* g1, const float* b1,
                          const float* m1, const float* v1,
                          const float* lb2, const float* g2, const float* b2,
                          const float* m2, const float* v2,
                          const float* __restrict__ w0, const float* __restrict__ w1,
                          const float* __restrict__ w2, const float* __restrict__ w3) {
    if (blockIdx.x >= NB_ED) {
        __shared__ float t[32][33];
        int b = blockIdx.x - NB_ED;
        const float* W; float* Wt; int K, N, bx, by;
        if (b < 32)       { W = w0; Wt = g_wt0; K = FF; N = D0; bx = b % 8;  by = b / 8; }
        else if (b < 96)  { W = w1; Wt = g_wt1; K = D0; N = D0; b -= 32;  bx = b % 8;  by = b / 8; }
        else if (b < 224) { W = w2; Wt = g_wt2; K = D0; N = D1; b -= 96;  bx = b % 16; by = b / 16; }
        else              { W = w3; Wt = g_wt3; K = D1; N = D1; b -= 224; bx = b % 16; by = b / 16; }
        int xx = threadIdx.x & 31, yy = threadIdx.x >> 5;
        int cx = bx * 32, cy = by * 32;
#pragma unroll
        for (int i = 0; i < 32; i += 8)
            t[yy + i][xx] = W[(size_t)(cy + yy + i) * N + cx + xx];
        __syncthreads();
#pragma unroll
        for (int i = 0; i < 32; i += 8)
            Wt[(size_t)(cx + yy + i) * K + cy + xx] = rtf32(t[xx][yy + i]);
        return;
    }
    int i = blockIdx.x * blockDim.x + threadIdx.x;
    if (i < NN * HH) { g_ls0[i] = 0.f; g_ld0[i] = 0.f; g_ls1[i] = 0.f; g_ld1[i] = 0.f; }
    if (i < EE && ew[i] == 1) atomicAdd(&g_deg[ei[EE + i]], 1);
    if (i < NN) {
        if (i == 0) {
            int c = batch[0];
            for (int g = 0; g <= c; g++) g_goff[g] = 0;
        } else {
            int p = batch[i - 1], c = batch[i];
            for (int g = p + 1; g <= c; g++) g_goff[g] = i;
        }
        if (i == NN - 1) {
            int c = batch[NN - 1];
            for (int g = c + 1; g <= GG; g++) g_goff[g] = NN;
        }
    }
    if (blockIdx.x == 0 && threadIdx.x < D0) {
        int t = threadIdx.x;
        float sc = g1[t] * rsqrtf(v1[t] + 1e-5f);
        g_sc1[t] = sc;
        g_sh1[t] = (lb1[t] - m1[t]) * sc + b1[t];
        float sc2 = g2[t] * rsqrtf(v2[t] + 1e-5f);
        g_sc2[t] = sc2;
        g_sh2[t] = (lb2[t] - m2[t]) * sc2 + b2[t];
    }
}

// ---------------- tf32 mma.sync GEMM: 256 thr, 8 warps @ 32x64, 4-stage ----------------
// EPI 0: plain fp32 store. EPI 1: rtf32(relu(acc*scale+shift)).
// EPI 2: plain store + fused attention logits. RNDA: round A fragments to tf32 in-register.
#define TG_STAGES 4
#define TG_LDS 20
#define TG_STAGE_FLOATS (2 * 128 * TG_LDS)
#define TG_SMEM (TG_STAGES * TG_STAGE_FLOATS * 4)

template <int EPI, int RNDA>
__global__ void __launch_bounds__(256, 2) tgemm(
    const float* __restrict__ A, const float* __restrict__ Bt,
    float* __restrict__ Cm, int M, int Nn, int K,
    const float* __restrict__ scale, const float* __restrict__ shift,
    const float* __restrict__ asrc, const float* __restrict__ adst,
    float* __restrict__ lsb, float* __restrict__ ldb)
{
    extern __shared__ float smem[];
    const int tid = threadIdx.x;
    const int wid = tid >> 5, lane = tid & 31;
    const int wm = wid & 3, wn = wid >> 2;
    const int lr = lane >> 2, lc = lane & 3;
    const int m0 = blockIdx.y * 128, n0 = blockIdx.x * 128;

    const int arow0 = tid >> 1;
    const int ac4 = (tid & 1) * 2;
    uint32_t sbase = smem_u32(smem);

    float acc[2][8][4];
#pragma unroll
    for (int i = 0; i < 2; i++)
#pragma unroll
        for (int j = 0; j < 8; j++)
#pragma unroll
            for (int q = 0; q < 4; q++) acc[i][j][q] = 0.f;

    const int nch = K >> 4;

    auto load_chunk = [&](int ch, int st) {
        int k0 = ch << 4;
        uint32_t sA = sbase + (uint32_t)(st * TG_STAGE_FLOATS) * 4u;
        uint32_t sB = sA + (uint32_t)(128 * TG_LDS) * 4u;
#pragma unroll
        for (int i = 0; i < 2; i++) {
            int row = arow0;
            int c4 = ac4 + i;
            int gr = m0 + row;
            int ok = (gr < M) ? 16 : 0;
            int grc = (gr < M) ? gr : (M - 1);
            cpa16(sA + (uint32_t)(row * TG_LDS + c4 * 4) * 4u,
                  A + (size_t)grc * K + k0 + c4 * 4, ok);
            cpa16(sB + (uint32_t)(row * TG_LDS + c4 * 4) * 4u,
                  Bt + (size_t)(n0 + row) * K + k0 + c4 * 4, 16);
        }
        cp_commit();
    };

    load_chunk(0, 0);
    if (nch > 1) load_chunk(1, 1);
    if (nch > 2) load_chunk(2, 2);

    for (int ch = 0; ch < nch; ch++) {
        int st = ch % TG_STAGES;
        cp_wait<TG_STAGES - 2>();
        __syncthreads();
        if (ch + 3 < nch) load_chunk(ch + 3, (ch + 3) % TG_STAGES);

        const float* Ab = smem + st * TG_STAGE_FLOATS + (wm * 32 + lr) * TG_LDS + lc;
        const float* Bb = smem + st * TG_STAGE_FLOATS + 128 * TG_LDS + (wn * 64 + lr) * TG_LDS + lc;
#pragma unroll
        for (int ks = 0; ks < 2; ks++) {
            int k0 = ks * 8;
            float a[2][4], b[8][2];
#pragma unroll
            for (int mt = 0; mt < 2; mt++) {
                a[mt][0] = Ab[(mt * 16) * TG_LDS + k0];
                a[mt][1] = Ab[(mt * 16 + 8) * TG_LDS + k0];
                a[mt][2] = Ab[(mt * 16) * TG_LDS + k0 + 4];
                a[mt][3] = Ab[(mt * 16 + 8) * TG_LDS + k0 + 4];
                if (RNDA) {
                    a[mt][0] = rtf32(a[mt][0]);
                    a[mt][1] = rtf32(a[mt][1]);
                    a[mt][2] = rtf32(a[mt][2]);
                    a[mt][3] = rtf32(a[mt][3]);
                }
            }
#pragma unroll
            for (int nt = 0; nt < 8; nt++) {
                b[nt][0] = Bb[(nt * 8) * TG_LDS + k0];
                b[nt][1] = Bb[(nt * 8) * TG_LDS + k0 + 4];
            }
#pragma unroll
            for (int mt = 0; mt < 2; mt++)
#pragma unroll
                for (int nt = 0; nt < 8; nt++)
                    mma_tf32(acc[mt][nt], a[mt], b[nt]);
        }
    }

    // ---- epilogue ----
    float sr[2][2] = {{0.f, 0.f}, {0.f, 0.f}};
    float dr[2][2] = {{0.f, 0.f}, {0.f, 0.f}};
#pragma unroll
    for (int mt = 0; mt < 2; mt++) {
        int row0 = m0 + wm * 32 + mt * 16 + lr;
#pragma unroll
        for (int nt = 0; nt < 8; nt++) {
            int col = n0 + wn * 64 + nt * 8 + lc * 2;
            float v0 = acc[mt][nt][0], v1 = acc[mt][nt][1];
            float v2 = acc[mt][nt][2], v3 = acc[mt][nt][3];
            if (EPI == 1) {
                float s0 = scale[col], s1 = scale[col + 1];
                float h0 = shift[col], h1 = shift[col + 1];
                v0 = rtf32(fmaxf(v0 * s0 + h0, 0.f));
                v1 = rtf32(fmaxf(v1 * s1 + h1, 0.f));
                v2 = rtf32(fmaxf(v2 * s0 + h0, 0.f));
                v3 = rtf32(fmaxf(v3 * s1 + h1, 0.f));
            }
            if (EPI == 2) {
                float as0 = asrc[col], as1 = asrc[col + 1];
                float ad0 = adst[col], ad1 = adst[col + 1];
                sr[mt][0] += v0 * as0 + v1 * as1;
                dr[mt][0] += v0 * ad0 + v1 * ad1;
                sr[mt][1] += v2 * as0 + v3 * as1;
                dr[mt][1] += v2 * ad0 + v3 * ad1;
            }
            if (row0 < M)
                *(float2*)(Cm + (size_t)row0 * Nn + col) = make_float2(v0, v1);
            if (row0 + 8 < M)
                *(float2*)(Cm + (size_t)(row0 + 8) * Nn + col) = make_float2(v2, v3);
        }
    }
    if (EPI == 2) {
        int h = (n0 >= 256) ? 1 : 0;
#pragma unroll
        for (int mt = 0; mt < 2; mt++)
#pragma unroll
            for (int half = 0; half < 2; half++) {
                float s = sr[mt][half], d = dr[mt][half];
                s += __shfl_xor_sync(0xffffffffu, s, 1);
                s += __shfl_xor_sync(0xffffffffu, s, 2);
                d += __shfl_xor_sync(0xffffffffu, d, 1);
                d += __shfl_xor_sync(0xffffffffu, d, 2);
                int row = m0 + wm * 32 + mt * 16 + lr + half * 8;
                if (lc == 0 && row < M) {
                    atomicAdd(&lsb[row * 2 + h], s);
                    atomicAdd(&ldb[row * 2 + h], d);
                }
            }
    }
}

// ---------------- CSR build (R6-proven path) ----------------
__global__ void scan_blocks() {
    __shared__ int s[512];
    int tid = threadIdx.x;
    int i = blockIdx.x * 512 + tid;
    int v = (i < NN) ? g_deg[i] : 0;
    if (i < NN) g_deg[i] = 0;        // re-zero for next call
    s[tid] = v;
    __syncthreads();
    for (int off = 1; off < 512; off <<= 1) {
        int u = (tid >= off) ? s[tid - off] : 0;
        __syncthreads();
        s[tid] += u;
        __syncthreads();
    }
    if (i < NN) g_off[i] = s[tid] - v;
    if (tid == 511) g_bsum[blockIdx.x] = s[511];
}

__global__ void scan_add2() {
    __shared__ int base;
    int i = blockIdx.x * blockDim.x + threadIdx.x;
    int sb = (int)((blockIdx.x * blockDim.x) >> 9);
    if (threadIdx.x == 0) {
        int a = 0;
        for (int b = 0; b < sb; b++) a += g_bsum[b];
        base = a;
        if (blockIdx.x == 0) {
            int tot = 0;
            int nblk = (NN + 511) / 512;
            for (int b = 0; b < nblk; b++) tot += g_bsum[b];
            g_off[NN] = tot;
        }
    }
    __syncthreads();
    if (i < NN) {
        int v = g_off[i] + base;
        g_off[i] = v;
        g_cur[i] = v;
    }
}

__global__ void scatter_kernel(const int* __restrict__ ei, const int* __restrict__ ew) {
    int e = blockIdx.x * blockDim.x + threadIdx.x;
    if (e < EE && ew[e] == 1) {
        int d = ei[EE + e];
        int pos = atomicAdd(&g_cur[d], 1);
        g_csr[pos] = ei[e];
    }
}

// ---------------- GAT aggregation: one WARP per node (R6-proven) ----------------
template <int ROUND>
__global__ void __launch_bounds__(256) gat_agg(const float* __restrict__ xw,
                                               const float* __restrict__ bias,
                                               float* __restrict__ out,
                                               const float* __restrict__ lsb,
                                               const float* __restrict__ ldb) {
    int gw = (blockIdx.x * blockDim.x + threadIdx.x) >> 5;
    if (gw >= NN) return;
    int lane = threadIdx.x & 31;
    int n = gw;
    int beg = g_off[n], end = g_off[n + 1];
    int deg = end - beg;
    float ld0 = ldb[n * 2], ld1 = ldb[n * 2 + 1];

    float4 a0 = make_float4(0.f, 0.f, 0.f, 0.f);
    float4 a1 = a0, a2 = a0, a3 = a0;
    float den0 = 0.f, den1 = 0.f;

#define ACC_EDGE(SL, P0V, P1V, J)                                               \
    {                                                                           \
        int s_ = __shfl_sync(0xffffffffu, (SL), (J));                           \
        float q0_ = __shfl_sync(0xffffffffu, (P0V), (J));                       \
        float q1_ = __shfl_sync(0xffffffffu, (P1V), (J));                       \
        const float4* row_ = (const float4*)(xw + (size_t)s_ * D1);             \
        float4 v0_ = row_[lane];                                                \
        float4 v1_ = row_[32 + lane];                                           \
        float4 v2_ = row_[64 + lane];                                           \
        float4 v3_ = row_[96 + lane];                                           \
        a0.x += q0_ * v0_.x; a0.y += q0_ * v0_.y; a0.z += q0_ * v0_.z; a0.w += q0_ * v0_.w; \
        a1.x += q0_ * v1_.x; a1.y += q0_ * v1_.y; a1.z += q0_ * v1_.z; a1.w += q0_ * v1_.w; \
        a2.x += q1_ * v2_.x; a2.y += q1_ * v2_.y; a2.z += q1_ * v2_.z; a2.w += q1_ * v2_.w; \
        a3.x += q1_ * v3_.x; a3.y += q1_ * v3_.y; a3.z += q1_ * v3_.z; a3.w += q1_ * v3_.w; \
    }

    if (deg <= 32) {
        int sl = 0;
        float e0 = -1e30f, e1 = -1e30f;
        if (lane < deg) {
            sl = g_csr[beg + lane];
            e0 = lsb[sl * 2] + ld0;     e0 = e0 > 0.f ? e0 : 0.2f * e0;
            e1 = lsb[sl * 2 + 1] + ld1; e1 = e1 > 0.f ? e1 : 0.2f * e1;
        }
        float m0 = e0, m1 = e1;
#pragma unroll
        for (int o = 16; o; o >>= 1) {
            m0 = fmaxf(m0, __shfl_xor_sync(0xffffffffu, m0, o));
            m1 = fmaxf(m1, __shfl_xor_sync(0xffffffffu, m1, o));
        }
        float p0 = (lane < deg) ? __expf(e0 - m0) : 0.f;
        float p1 = (lane < deg) ? __expf(e1 - m1) : 0.f;
        den0 = p0; den1 = p1;
        int j = 0;
        for (; j + 1 < deg; j += 2) { ACC_EDGE(sl, p0, p1, j); ACC_EDGE(sl, p0, p1, j + 1); }
        if (j < deg) ACC_EDGE(sl, p0, p1, j);
    } else {
        float m0 = -1e30f, m1 = -1e30f;
        for (int i = lane; i < deg; i += 32) {
            int s = g_csr[beg + i];
            float e0 = lsb[s * 2] + ld0;     e0 = e0 > 0.f ? e0 : 0.2f * e0;
            float e1 = lsb[s * 2 + 1] + ld1; e1 = e1 > 0.f ? e1 : 0.2f * e1;
            m0 = fmaxf(m0, e0);
            m1 = fmaxf(m1, e1);
        }
#pragma unroll
        for (int o = 16; o; o >>= 1) {
            m0 = fmaxf(m0, __shfl_xor_sync(0xffffffffu, m0, o));
            m1 = fmaxf(m1, __shfl_xor_sync(0xffffffffu, m1, o));
        }
        for (int base = 0; base < deg; base += 32) {
            int i = base + lane;
            float p0 = 0.f, p1 = 0.f;
            int sl = 0;
            if (i < deg) {
                sl = g_csr[beg + i];
                float e0 = lsb[sl * 2] + ld0;     e0 = e0 > 0.f ? e0 : 0.2f * e0;
                float e1 = lsb[sl * 2 + 1] + ld1; e1 = e1 > 0.f ? e1 : 0.2f * e1;
                p0 = __expf(e0 - m0);
                p1 = __expf(e1 - m1);
            }
            den0 += p0; den1 += p1;
            int cnt = min(32, deg - base);
            int j = 0;
            for (; j + 1 < cnt; j += 2) { ACC_EDGE(sl, p0, p1, j); ACC_EDGE(sl, p0, p1, j + 1); }
            if (j < cnt) ACC_EDGE(sl, p0, p1, j);
        }
    }
#undef ACC_EDGE

#pragma unroll
    for (int o = 16; o; o >>= 1) {
        den0 += __shfl_xor_sync(0xffffffffu, den0, o);
        den1 += __shfl_xor_sync(0xffffffffu, den1, o);
    }
    float r0 = 1.f / (den0 + 1e-16f), r1 = 1.f / (den1 + 1e-16f);

    const float4* bi = (const float4*)bias;
    float4* op = (float4*)(out + (size_t)n * D1);
    float4 b0 = bi[lane], b1 = bi[32 + lane], b2 = bi[64 + lane], b3 = bi[96 + lane];
    float4 o0 = make_float4(a0.x * r0 + b0.x, a0.y * r0 + b0.y, a0.z * r0 + b0.z, a0.w * r0 + b0.w);
    float4 o1 = make_float4(a1.x * r0 + b1.x, a1.y * r0 + b1.y, a1.z * r0 + b1.z, a1.w * r0 + b1.w);
    float4 o2 = make_float4(a2.x * r1 + b2.x, a2.y * r1 + b2.y, a2.z * r1 + b2.z, a2.w * r1 + b2.w);
    float4 o3 = make_float4(a3.x * r1 + b3.x, a3.y * r1 + b3.y, a3.z * r1 + b3.z, a3.w * r1 + b3.w);
    if (ROUND) {
        o0 = make_float4(rtf32(o0.x), rtf32(o0.y), rtf32(o0.z), rtf32(o0.w));
        o1 = make_float4(rtf32(o1.x), rtf32(o1.y), rtf32(o1.z), rtf32(o1.w));
        o2 = make_float4(rtf32(o2.x), rtf32(o2.y), rtf32(o2.z), rtf32(o2.w));
        o3 = make_float4(rtf32(o3.x), rtf32(o3.y), rtf32(o3.z), rtf32(o3.w));
    }
    op[lane] = o0;
    op[32 + lane] = o1;
    op[64 + lane] = o2;
    op[96 + lane] = o3;
}

// ---------------- final head: 16 blocks x 8 graphs, w1 reused across graphs ----------------
#define FH_G 8
__global__ void __launch_bounds__(512) final_head(
    const float* __restrict__ h,
    const float* __restrict__ bn3g, const float* __restrict__ bn3b,
    const float* __restrict__ bn3m, const float* __restrict__ bn3v,
    const float* __restrict__ w1, const float* __restrict__ b1,
    const float* __restrict__ w2, const float* __restrict__ b2,
    float* __restrict__ out)
{
    int g0 = blockIdx.x * FH_G, t = threadIdx.x;
    __shared__ float z[FH_G][512];
    __shared__ float s1[FH_G][512];

    // pooling + BN + ReLU for 8 graphs
    float sc = bn3g[t] * rsqrtf(bn3v[t] + 1e-5f);
    float bm = bn3m[t], bb = bn3b[t];
#pragma unroll
    for (int gi = 0; gi < FH_G; gi++) {
        int g = g0 + gi;
        int s = g_goff[g], e = g_goff[g + 1];
        float a0 = 0.f, a1 = 0.f, a2 = 0.f, a3 = 0.f;
        int n = s;
        for (; n + 3 < e; n += 4) {
            a0 += h[(size_t)n * D1 + t];
            a1 += h[(size_t)(n + 1) * D1 + t];
            a2 += h[(size_t)(n + 2) * D1 + t];
            a3 += h[(size_t)(n + 3) * D1 + t];
        }
        for (; n < e; n++) a0 += h[(size_t)n * D1 + t];
        float pv = (a0 + a1 + a2 + a3) / fmaxf((float)(e - s), 1.0f);
        z[gi][t] = fmaxf((pv - bm) * sc + bb, 0.f);
    }
    __syncthreads();

    // linear1: each thread owns output column t for all 8 graphs
    float acc[FH_G] = {};
    for (int k = 0; k < 512; k++) {
        float w = w1[(size_t)k * 512 + t];
#pragma unroll
        for (int gi = 0; gi < FH_G; gi++)
            acc[gi] += z[gi][k] * w;
    }
    float bv = b1[t];
#pragma unroll
    for (int gi = 0; gi < FH_G; gi++)
        s1[gi][t] = fmaxf(acc[gi] + bv, 0.f);
    __syncthreads();

    // linear2: 10 outputs per graph, warp-reduced
    if (t < NC * 32) {
        int col = t >> 5, lane = t & 31;
#pragma unroll
        for (int gi = 0; gi < FH_G; gi++) {
            float sv = 0.f;
            for (int k = lane; k < 512; k += 32) sv += s1[gi][k] * w2[k * NC + col];
#pragma unroll
            for (int o = 16; o; o >>= 1) sv += __shfl_xor_sync(0xffffffffu, sv, o);
            if (!lane) out[(g0 + gi) * NC + col] = sv + b2[col];
        }
    }
}

// ---------------- host launcher ----------------
extern "C" void kernel_launch(void* const* d_in, const int* in_sizes, int n_in,
                              void* d_out, int out_size) {
    const float* x        = (const float*)d_in[0];
    const int*   ei       = (const int*)d_in[1];
    const int*   ew       = (const int*)d_in[2];
    const int*   batch    = (const int*)d_in[3];
    const float* mlp_w1   = (const float*)d_in[4];
    const float* mlp_b1   = (const float*)d_in[5];
    const float* bn1_g    = (const float*)d_in[6];
    const float* bn1_b    = (const float*)d_in[7];
    const float* bn1_m    = (const float*)d_in[8];
    const float* bn1_v    = (const float*)d_in[9];
    const float* mlp_w2   = (const float*)d_in[10];
    const float* mlp_b2   = (const float*)d_in[11];
    const float* bn2_g    = (const float*)d_in[12];
    const float* bn2_b    = (const float*)d_in[13];
    const float* bn2_m    = (const float*)d_in[14];
    const float* bn2_v    = (const float*)d_in[15];
    const float* gat0_w   = (const float*)d_in[16];
    const float* gat0_as  = (const float*)d_in[17];
    const float* gat0_ad  = (const float*)d_in[18];
    const float* gat0_bi  = (const float*)d_in[19];
    const float* gat1_w   = (const float*)d_in[20];
    const float* gat1_as  = (const float*)d_in[21];
    const float* gat1_ad  = (const float*)d_in[22];
    const float* gat1_bi  = (const float*)d_in[23];
    const float* bn3_g    = (const float*)d_in[24];
    const float* bn3_b    = (const float*)d_in[25];
    const float* bn3_m    = (const float*)d_in[26];
    const float* bn3_v    = (const float*)d_in[27];
    const float* fin_w1   = (const float*)d_in[28];
    const float* fin_b1   = (const float*)d_in[29];
    const float* fin_w2   = (const float*)d_in[30];
    const float* fin_b2   = (const float*)d_in[31];
    float* out = (float*)d_out;

    float *hp_h1, *hp_h2, *hp_xw, *hp_h3, *hp_h4;
    float *hp_wt0, *hp_wt1, *hp_wt2, *hp_wt3;
    float *hp_sc1, *hp_sh1, *hp_sc2, *hp_sh2;
    float *hp_ls0, *hp_ld0, *hp_ls1, *hp_ld1;
    cudaGetSymbolAddress((void**)&hp_h1, g_h1);
    cudaGetSymbolAddress((void**)&hp_h2, g_h2);
    cudaGetSymbolAddress((void**)&hp_xw, g_xw);
    cudaGetSymbolAddress((void**)&hp_h3, g_h3);
    cudaGetSymbolAddress((void**)&hp_h4, g_h4);
    cudaGetSymbolAddress((void**)&hp_wt0, g_wt0);
    cudaGetSymbolAddress((void**)&hp_wt1, g_wt1);
    cudaGetSymbolAddress((void**)&hp_wt2, g_wt2);
    cudaGetSymbolAddress((void**)&hp_wt3, g_wt3);
    cudaGetSymbolAddress((void**)&hp_sc1, g_sc1);
    cudaGetSymbolAddress((void**)&hp_sh1, g_sh1);
    cudaGetSymbolAddress((void**)&hp_sc2, g_sc2);
    cudaGetSymbolAddress((void**)&hp_sh2, g_sh2);
    cudaGetSymbolAddress((void**)&hp_ls0, g_ls0);
    cudaGetSymbolAddress((void**)&hp_ld0, g_ld0);
    cudaGetSymbolAddress((void**)&hp_ls1, g_ls1);
    cudaGetSymbolAddress((void**)&hp_ld1, g_ld1);

    cudaFuncSetAttribute((const void*)tgemm<0, 0>, cudaFuncAttributeMaxDynamicSharedMemorySize, TG_SMEM);
    cudaFuncSetAttribute((const void*)tgemm<1, 0>, cudaFuncAttributeMaxDynamicSharedMemorySize, TG_SMEM);
    cudaFuncSetAttribute((const void*)tgemm<1, 1>, cudaFuncAttributeMaxDynamicSharedMemorySize, TG_SMEM);
    cudaFuncSetAttribute((const void*)tgemm<2, 0>, cudaFuncAttributeMaxDynamicSharedMemorySize, TG_SMEM);

    // 1) prepass (hist + zeros + bounds + BN fold + transposes) + CSR
    fused_pre<<<NB_ED + NB_TR, 256>>>(batch, ei, ew,
        mlp_b1, bn1_g, bn1_b, bn1_m, bn1_v,
        mlp_b2, bn2_g, bn2_b, bn2_m, bn2_v,
        mlp_w1, mlp_w2, gat0_w, gat1_w);
    scan_blocks<<<(NN + 511) / 512, 512>>>();
    scan_add2<<<(NN + 255) / 256, 256>>>();
    scatter_kernel<<<(EE + 255) / 256, 256>>>(ei, ew);

    const int MB = (NN + 127) / 128;  // 157
    const int AGG_BLOCKS = (NN * 32 + 255) / 256;

    // 2) node MLP (GEMM1 reads raw x, rounds A in-register)
    tgemm<1, 1><<<dim3(D0 / 128, MB), 256, TG_SMEM>>>(x, hp_wt0, hp_h1, NN, D0, FF,
        hp_sc1, hp_sh1, nullptr, nullptr, nullptr, nullptr);
    tgemm<1, 0><<<dim3(D0 / 128, MB), 256, TG_SMEM>>>(hp_h1, hp_wt1, hp_h2, NN, D0, D0,
        hp_sc2, hp_sh2, nullptr, nullptr, nullptr, nullptr);

    // 3) GAT layer 0
    tgemm<2, 0><<<dim3(D1 / 128, MB), 256, TG_SMEM>>>(hp_h2, hp_wt2, hp_xw, NN, D1, D0,
        nullptr, nullptr, gat0_as, gat0_ad, hp_ls0, hp_ld0);
    gat_agg<1><<<AGG_BLOCKS, 256>>>(hp_xw, gat0_bi, hp_h3, hp_ls0, hp_ld0);

    // 4) GAT layer 1
    tgemm<2, 0><<<dim3(D1 / 128, MB), 256, TG_SMEM>>>(hp_h3, hp_wt3, hp_xw, NN, D1, D1,
        nullptr, nullptr, gat1_as, gat1_ad, hp_ls1, hp_ld1);
    gat_agg<0><<<AGG_BLOCKS, 256>>>(hp_xw, gat1_bi, hp_h4, hp_ls1, hp_ld1);

    // 5) pooled final head (8 graphs per block)
    final_head<<<GG / FH_G, 512>>>(hp_h4, bn3_g, bn3_b, bn3_m, bn3_v,
                                   fin_w1, fin_b1, fin_w2, fin_b2, out);
}

// round 11
// speedup vs baseline: 1.4401x; 1.4401x over previous
#include <cuda_runtime.h>
#include <cstdint>

#define NN 20000
#define EE 320000
#define FF 128
#define D0 256
#define D1 512
#define HH 2
#define CC 256
#define GG 128
#define NC 10

// ---------------- scratch (device globals; zero-initialized at load) ----------------
__device__ float g_rx[NN * FF];
__device__ float g_h1[NN * D0];
__device__ float g_h2[NN * D0];
__device__ float g_xw[NN * D1];
__device__ float g_h3[NN * D1];
__device__ float g_h4[NN * D1];
__device__ float g_wt0[FF * D0];
__device__ float g_wt1[D0 * D0];
__device__ float g_wt2[D0 * D1];
__device__ float g_wt3[D1 * D1];
__device__ float g_ls0[NN * HH], g_ld0[NN * HH];
__device__ float g_ls1[NN * HH], g_ld1[NN * HH];
__device__ int   g_deg[NN];      // invariant: all-zero at kernel_launch entry
__device__ int   g_off[NN + 1];
__device__ int   g_cur[NN];
__device__ int   g_csr[EE];
__device__ int   g_bsum[64];
__device__ int   g_goff[GG + 1];
__device__ float g_sc1[D0], g_sh1[D0], g_sc2[D0], g_sh2[D0];

// ---------------- small helpers ----------------
__device__ __forceinline__ float rtf32(float x) {
    uint32_t u;
    asm("cvt.rna.tf32.f32 %0, %1;" : "=r"(u) : "f"(x));
    return __uint_as_float(u);
}
__device__ __forceinline__ uint32_t smem_u32(const void* p) {
    uint32_t a;
    asm("{ .reg .u64 t; cvta.to.shared.u64 t, %1; cvt.u32.u64 %0, t; }" : "=r"(a) : "l"(p));
    return a;
}
__device__ __forceinline__ void cpa16(uint32_t dst, const void* src, int sz) {
    asm volatile("cp.async.cg.shared.global [%0], [%1], 16, %2;"
                 :: "r"(dst), "l"(src), "r"(sz));
}
__device__ __forceinline__ void cp_commit() {
    asm volatile("cp.async.commit_group;");
}
template <int N>
__device__ __forceinline__ void cp_wait() {
    asm volatile("cp.async.wait_group %0;" :: "n"(N));
}
__device__ __forceinline__ void mma_tf32(float* d, const float* a, const float* b) {
    asm volatile(
        "mma.sync.aligned.m16n8k8.row.col.f32.tf32.tf32.f32 "
        "{%0,%1,%2,%3}, {%4,%5,%6,%7}, {%8,%9}, {%0,%1,%2,%3};"
        : "+f"(d[0]), "+f"(d[1]), "+f"(d[2]), "+f"(d[3])
        : "r"(__float_as_uint(a[0])), "r"(__float_as_uint(a[1])),
          "r"(__float_as_uint(a[2])), "r"(__float_as_uint(a[3])),
          "r"(__float_as_uint(b[0])), "r"(__float_as_uint(b[1])));
}

// ---------------- fused prepass (K5-identical) ----------------
#define NB_RX ((NN * FF + 255) / 256)   // 10000
#define NB_TR 480

__global__ void fused_pre(const float* __restrict__ x, const int* __restrict__ batch,
                          const int* __restrict__ ei, const int* __restrict__ ew,
                          const float* lb1, const float* g1, const float* b1,
                          const float* m1, const float* v1,
                          const float* lb2, const float* g2, const float* b2,
                          const float* m2, const float* v2,
                          const float* __restrict__ w0, const float* __restrict__ w1,
                          const float* __restrict__ w2, const float* __restrict__ w3) {
    if (blockIdx.x >= NB_RX) {
        __shared__ float t[32][33];
        int b = blockIdx.x - NB_RX;
        const float* W; float* Wt; int K, N, bx, by;
        if (b < 32)       { W = w0; Wt = g_wt0; K = FF; N = D0; bx = b % 8;  by = b / 8; }
        else if (b < 96)  { W = w1; Wt = g_wt1; K = D0; N = D0; b -= 32;  bx = b % 8;  by = b / 8; }
        else if (b < 224) { W = w2; Wt = g_wt2; K = D0; N = D1; b -= 96;  bx = b % 16; by = b / 16; }
        else              { W = w3; Wt = g_wt3; K = D1; N = D1; b -= 224; bx = b % 16; by = b / 16; }
        int xx = threadIdx.x & 31, yy = threadIdx.x >> 5;
        int cx = bx * 32, cy = by * 32;
#pragma unroll
        for (int i = 0; i < 32; i += 8)
            t[yy + i][xx] = W[(size_t)(cy + yy + i) * N + cx + xx];
        __syncthreads();
#pragma unroll
        for (int i = 0; i < 32; i += 8)
            Wt[(size_t)(cx + yy + i) * K + cy + xx] = rtf32(t[xx][yy + i]);
        return;
    }
    int i = blockIdx.x * blockDim.x + threadIdx.x;
    if (i < NN * FF) g_rx[i] = rtf32(x[i]);
    if (i < NN * HH) { g_ls0[i] = 0.f; g_ld0[i] = 0.f; g_ls1[i] = 0.f; g_ld1[i] = 0.f; }
    if (i < EE && ew[i] == 1) atomicAdd(&g_deg[ei[EE + i]], 1);
    if (i < NN) {
        if (i == 0) {
            int c = batch[0];
            for (int g = 0; g <= c; g++) g_goff[g] = 0;
        } else {
            int p = batch[i - 1], c = batch[i];
            for (int g = p + 1; g <= c; g++) g_goff[g] = i;
        }
        if (i == NN - 1) {
            int c = batch[NN - 1];
            for (int g = c + 1; g <= GG; g++) g_goff[g] = NN;
        }
    }
    if (blockIdx.x == 0 && threadIdx.x < D0) {
        int t = threadIdx.x;
        float sc = g1[t] * rsqrtf(v1[t] + 1e-5f);
        g_sc1[t] = sc;
        g_sh1[t] = (lb1[t] - m1[t]) * sc + b1[t];
        float sc2 = g2[t] * rsqrtf(v2[t] + 1e-5f);
        g_sc2[t] = sc2;
        g_sh2[t] = (lb2[t] - m2[t]) * sc2 + b2[t];
    }
}

// ---------------- tf32 mma.sync GEMM: CTA 128x64, 8 warps @ 32x32, 4-stage, 3 CTA/SM ----------------
#define TG_STAGES 4
#define TG_LDS 20
#define TG_STAGE_FLOATS ((128 + 64) * TG_LDS)       // 3840
#define TG_SMEM (TG_STAGES * TG_STAGE_FLOATS * 4)   // 61440

template <int EPI>
__global__ void __launch_bounds__(256, 3) tgemm(
    const float* __restrict__ A, const float* __restrict__ Bt,
    float* __restrict__ Cm, int M, int Nn, int K,
    const float* __restrict__ scale, const float* __restrict__ shift,
    const float* __restrict__ asrc, const float* __restrict__ adst,
    float* __restrict__ lsb, float* __restrict__ ldb)
{
    extern __shared__ float smem[];
    const int tid = threadIdx.x;
    const int wid = tid >> 5, lane = tid & 31;
    const int wm = wid & 3, wn = wid >> 2;       // 4 m-warps x 2 n-warps
    const int lr = lane >> 2, lc = lane & 3;
    const int m0 = blockIdx.y * 128, n0 = blockIdx.x * 64;

    // A loads: 128 rows, 2 float4 per thread.  B loads: 64 rows, 1 float4 per thread.
    const int arow = tid >> 1;
    const int ac4 = (tid & 1) * 2;
    const int brow = tid >> 2;
    const int bc4 = tid & 3;
    uint32_t sbase = smem_u32(smem);

    float acc[2][4][4];
#pragma unroll
    for (int i = 0; i < 2; i++)
#pragma unroll
        for (int j = 0; j < 4; j++)
#pragma unroll
            for (int q = 0; q < 4; q++) acc[i][j][q] = 0.f;

    const int nch = K >> 4;

    auto load_chunk = [&](int ch, int st) {
        int k0 = ch << 4;
        uint32_t sA = sbase + (uint32_t)(st * TG_STAGE_FLOATS) * 4u;
        uint32_t sB = sA + (uint32_t)(128 * TG_LDS) * 4u;
        // A: two float4 per thread
        int gr = m0 + arow;
        int ok = (gr < M) ? 16 : 0;
        int grc = (gr < M) ? gr : (M - 1);
#pragma unroll
        for (int i = 0; i < 2; i++) {
            int c4 = ac4 + i;
            cpa16(sA + (uint32_t)(arow * TG_LDS + c4 * 4) * 4u,
                  A + (size_t)grc * K + k0 + c4 * 4, ok);
        }
        // B: one float4 per thread (rows always valid; Nn multiple of 64)
        cpa16(sB + (uint32_t)(brow * TG_LDS + bc4 * 4) * 4u,
              Bt + (size_t)(n0 + brow) * K + k0 + bc4 * 4, 16);
        cp_commit();
    };

    load_chunk(0, 0);
    if (nch > 1) load_chunk(1, 1);
    if (nch > 2) load_chunk(2, 2);

    for (int ch = 0; ch < nch; ch++) {
        int st = ch % TG_STAGES;
        cp_wait<TG_STAGES - 2>();
        __syncthreads();
        if (ch + 3 < nch) load_chunk(ch + 3, (ch + 3) % TG_STAGES);

        const float* Ab = smem + st * TG_STAGE_FLOATS + (wm * 32 + lr) * TG_LDS + lc;
        const float* Bb = smem + st * TG_STAGE_FLOATS + 128 * TG_LDS + (wn * 32 + lr) * TG_LDS + lc;
#pragma unroll
        for (int ks = 0; ks < 2; ks++) {
            int k0 = ks * 8;
            float a[2][4], b[4][2];
#pragma unroll
            for (int mt = 0; mt < 2; mt++) {
                a[mt][0] = Ab[(mt * 16) * TG_LDS + k0];
                a[mt][1] = Ab[(mt * 16 + 8) * TG_LDS + k0];
                a[mt][2] = Ab[(mt * 16) * TG_LDS + k0 + 4];
                a[mt][3] = Ab[(mt * 16 + 8) * TG_LDS + k0 + 4];
            }
#pragma unroll
            for (int nt = 0; nt < 4; nt++) {
                b[nt][0] = Bb[(nt * 8) * TG_LDS + k0];
                b[nt][1] = Bb[(nt * 8) * TG_LDS + k0 + 4];
            }
#pragma unroll
            for (int mt = 0; mt < 2; mt++)
#pragma unroll
                for (int nt = 0; nt < 4; nt++)
                    mma_tf32(acc[mt][nt], a[mt], b[nt]);
        }
    }

    // ---- epilogue ----
    float sr[2][2] = {{0.f, 0.f}, {0.f, 0.f}};
    float dr[2][2] = {{0.f, 0.f}, {0.f, 0.f}};
#pragma unroll
    for (int mt = 0; mt < 2; mt++) {
        int row0 = m0 + wm * 32 + mt * 16 + lr;
#pragma unroll
        for (int nt = 0; nt < 4; nt++) {
            int col = n0 + wn * 32 + nt * 8 + lc * 2;
            float v0 = acc[mt][nt][0], v1 = acc[mt][nt][1];
            float v2 = acc[mt][nt][2], v3 = acc[mt][nt][3];
            if (EPI == 1) {
                float s0 = scale[col], s1 = scale[col + 1];
                float h0 = shift[col], h1 = shift[col + 1];
                v0 = rtf32(fmaxf(v0 * s0 + h0, 0.f));
                v1 = rtf32(fmaxf(v1 * s1 + h1, 0.f));
                v2 = rtf32(fmaxf(v2 * s0 + h0, 0.f));
                v3 = rtf32(fmaxf(v3 * s1 + h1, 0.f));
            }
            if (EPI == 2) {
                float as0 = asrc[col], as1 = asrc[col + 1];
                float ad0 = adst[col], ad1 = adst[col + 1];
                sr[mt][0] += v0 * as0 + v1 * as1;
                dr[mt][0] += v0 * ad0 + v1 * ad1;
                sr[mt][1] += v2 * as0 + v3 * as1;
                dr[mt][1] += v2 * ad0 + v3 * ad1;
            }
            if (row0 < M)
                *(float2*)(Cm + (size_t)row0 * Nn + col) = make_float2(v0, v1);
            if (row0 + 8 < M)
                *(float2*)(Cm + (size_t)(row0 + 8) * Nn + col) = make_float2(v2, v3);
        }
    }
    if (EPI == 2) {
        int h = (n0 >= 256) ? 1 : 0;
#pragma unroll
        for (int mt = 0; mt < 2; mt++)
#pragma unroll
            for (int half = 0; half < 2; half++) {
                float s = sr[mt][half], d = dr[mt][half];
                s += __shfl_xor_sync(0xffffffffu, s, 1);
                s += __shfl_xor_sync(0xffffffffu, s, 2);
                d += __shfl_xor_sync(0xffffffffu, d, 1);
                d += __shfl_xor_sync(0xffffffffu, d, 2);
                int row = m0 + wm * 32 + mt * 16 + lr + half * 8;
                if (lc == 0 && row < M) {
                    atomicAdd(&lsb[row * 2 + h], s);
                    atomicAdd(&ldb[row * 2 + h], d);
                }
            }
    }
}

// ---------------- CSR build (K5-identical) ----------------
__global__ void scan_blocks() {
    __shared__ int s[512];
    int tid = threadIdx.x;
    int i = blockIdx.x * 512 + tid;
    int v = (i < NN) ? g_deg[i] : 0;
    if (i < NN) g_deg[i] = 0;
    s[tid] = v;
    __syncthreads();
    for (int off = 1; off < 512; off <<= 1) {
        int u = (tid >= off) ? s[tid - off] : 0;
        __syncthreads();
        s[tid] += u;
        __syncthreads();
    }
    if (i < NN) g_off[i] = s[tid] - v;
    if (tid == 511) g_bsum[blockIdx.x] = s[511];
}

__global__ void scan_add2() {
    __shared__ int base;
    int i = blockIdx.x * blockDim.x + threadIdx.x;
    int sb = (int)((blockIdx.x * blockDim.x) >> 9);
    if (threadIdx.x == 0) {
        int a = 0;
        for (int b = 0; b < sb; b++) a += g_bsum[b];
        base = a;
        if (blockIdx.x == 0) {
            int tot = 0;
            int nblk = (NN + 511) / 512;
            for (int b = 0; b < nblk; b++) tot += g_bsum[b];
            g_off[NN] = tot;
        }
    }
    __syncthreads();
    if (i < NN) {
        int v = g_off[i] + base;
        g_off[i] = v;
        g_cur[i] = v;
    }
}

__global__ void scatter_kernel(const int* __restrict__ ei, const int* __restrict__ ew) {
    int e = blockIdx.x * blockDim.x + threadIdx.x;
    if (e < EE && ew[e] == 1) {
        int d = ei[EE + e];
        int pos = atomicAdd(&g_cur[d], 1);
        g_csr[pos] = ei[e];
    }
}

// ---------------- GAT aggregation: one WARP per node (K5-identical) ----------------
template <int ROUND>
__global__ void __launch_bounds__(256) gat_agg(const float* __restrict__ xw,
                                               const float* __restrict__ bias,
                                               float* __restrict__ out,
                                               const float* __restrict__ lsb,
                                               const float* __restrict__ ldb) {
    int gw = (blockIdx.x * blockDim.x + threadIdx.x) >> 5;
    if (gw >= NN) return;
    int lane = threadIdx.x & 31;
    int n = gw;
    int beg = g_off[n], end = g_off[n + 1];
    int deg = end - beg;
    float ld0 = ldb[n * 2], ld1 = ldb[n * 2 + 1];

    float4 a0 = make_float4(0.f, 0.f, 0.f, 0.f);
    float4 a1 = a0, a2 = a0, a3 = a0;
    float den0 = 0.f, den1 = 0.f;

#define ACC_EDGE(SL, P0V, P1V, J)                                               \
    {                                                                           \
        int s_ = __shfl_sync(0xffffffffu, (SL), (J));                           \
        float q0_ = __shfl_sync(0xffffffffu, (P0V), (J));                       \
        float q1_ = __shfl_sync(0xffffffffu, (P1V), (J));                       \
        const float4* row_ = (const float4*)(xw + (size_t)s_ * D1);             \
        float4 v0_ = row_[lane];                                                \
        float4 v1_ = row_[32 + lane];                                           \
        float4 v2_ = row_[64 + lane];                                           \
        float4 v3_ = row_[96 + lane];                                           \
        a0.x += q0_ * v0_.x; a0.y += q0_ * v0_.y; a0.z += q0_ * v0_.z; a0.w += q0_ * v0_.w; \
        a1.x += q0_ * v1_.x; a1.y += q0_ * v1_.y; a1.z += q0_ * v1_.z; a1.w += q0_ * v1_.w; \
        a2.x += q1_ * v2_.x; a2.y += q1_ * v2_.y; a2.z += q1_ * v2_.z; a2.w += q1_ * v2_.w; \
        a3.x += q1_ * v3_.x; a3.y += q1_ * v3_.y; a3.z += q1_ * v3_.z; a3.w += q1_ * v3_.w; \
    }

    if (deg <= 32) {
        int sl = 0;
        float e0 = -1e30f, e1 = -1e30f;
        if (lane < deg) {
            sl = g_csr[beg + lane];
            e0 = lsb[sl * 2] + ld0;     e0 = e0 > 0.f ? e0 : 0.2f * e0;
            e1 = lsb[sl * 2 + 1] + ld1; e1 = e1 > 0.f ? e1 : 0.2f * e1;
        }
        float m0 = e0, m1 = e1;
#pragma unroll
        for (int o = 16; o; o >>= 1) {
            m0 = fmaxf(m0, __shfl_xor_sync(0xffffffffu, m0, o));
            m1 = fmaxf(m1, __shfl_xor_sync(0xffffffffu, m1, o));
        }
        float p0 = (lane < deg) ? __expf(e0 - m0) : 0.f;
        float p1 = (lane < deg) ? __expf(e1 - m1) : 0.f;
        den0 = p0; den1 = p1;
        int j = 0;
        for (; j + 1 < deg; j += 2) { ACC_EDGE(sl, p0, p1, j); ACC_EDGE(sl, p0, p1, j + 1); }
        if (j < deg) ACC_EDGE(sl, p0, p1, j);
    } else {
        float m0 = -1e30f, m1 = -1e30f;
        for (int i = lane; i < deg; i += 32) {
            int s = g_csr[beg + i];
            float e0 = lsb[s * 2] + ld0;     e0 = e0 > 0.f ? e0 : 0.2f * e0;
            float e1 = lsb[s * 2 + 1] + ld1; e1 = e1 > 0.f ? e1 : 0.2f * e1;
            m0 = fmaxf(m0, e0);
            m1 = fmaxf(m1, e1);
        }
#pragma unroll
        for (int o = 16; o; o >>= 1) {
            m0 = fmaxf(m0, __shfl_xor_sync(0xffffffffu, m0, o));
            m1 = fmaxf(m1, __shfl_xor_sync(0xffffffffu, m1, o));
        }
        for (int base = 0; base < deg; base += 32) {
            int i = base + lane;
            float p0 = 0.f, p1 = 0.f;
            int sl = 0;
            if (i < deg) {
                sl = g_csr[beg + i];
                float e0 = lsb[sl * 2] + ld0;     e0 = e0 > 0.f ? e0 : 0.2f * e0;
                float e1 = lsb[sl * 2 + 1] + ld1; e1 = e1 > 0.f ? e1 : 0.2f * e1;
                p0 = __expf(e0 - m0);
                p1 = __expf(e1 - m1);
            }
            den0 += p0; den1 += p1;
            int cnt = min(32, deg - base);
            int j = 0;
            for (; j + 1 < cnt; j += 2) { ACC_EDGE(sl, p0, p1, j); ACC_EDGE(sl, p0, p1, j + 1); }
            if (j < cnt) ACC_EDGE(sl, p0, p1, j);
        }
    }
#undef ACC_EDGE

#pragma unroll
    for (int o = 16; o; o >>= 1) {
        den0 += __shfl_xor_sync(0xffffffffu, den0, o);
        den1 += __shfl_xor_sync(0xffffffffu, den1, o);
    }
    float r0 = 1.f / (den0 + 1e-16f), r1 = 1.f / (den1 + 1e-16f);

    const float4* bi = (const float4*)bias;
    float4* op = (float4*)(out + (size_t)n * D1);
    float4 b0 = bi[lane], b1 = bi[32 + lane], b2 = bi[64 + lane], b3 = bi[96 + lane];
    float4 o0 = make_float4(a0.x * r0 + b0.x, a0.y * r0 + b0.y, a0.z * r0 + b0.z, a0.w * r0 + b0.w);
    float4 o1 = make_float4(a1.x * r0 + b1.x, a1.y * r0 + b1.y, a1.z * r0 + b1.z, a1.w * r0 + b1.w);
    float4 o2 = make_float4(a2.x * r1 + b2.x, a2.y * r1 + b2.y, a2.z * r1 + b2.z, a2.w * r1 + b2.w);
    float4 o3 = make_float4(a3.x * r1 + b3.x, a3.y * r1 + b3.y, a3.z * r1 + b3.z, a3.w * r1 + b3.w);
    if (ROUND) {
        o0 = make_float4(rtf32(o0.x), rtf32(o0.y), rtf32(o0.z), rtf32(o0.w));
        o1 = make_float4(rtf32(o1.x), rtf32(o1.y), rtf32(o1.z), rtf32(o1.w));
        o2 = make_float4(rtf32(o2.x), rtf32(o2.y), rtf32(o2.z), rtf32(o2.w));
        o3 = make_float4(rtf32(o3.x), rtf32(o3.y), rtf32(o3.z), rtf32(o3.w));
    }
    op[lane] = o0;
    op[32 + lane] = o1;
    op[64 + lane] = o2;
    op[96 + lane] = o3;
}

// ---------------- final head (K5-identical: 128 blocks, pooling fused) ----------------
__global__ void __launch_bounds__(512) final_head(
    const float* __restrict__ h,
    const float* __restrict__ bn3g, const float* __restrict__ bn3b,
    const float* __restrict__ bn3m, const float* __restrict__ bn3v,
    const float* __restrict__ w1, const float* __restrict__ b1,
    const float* __restrict__ w2, const float* __restrict__ b2,
    float* __restrict__ out)
{
    int g = blockIdx.x, t = threadIdx.x;
    __shared__ float z[512];
    __shared__ float s1[512];
    int s = g_goff[g], e = g_goff[g + 1];
    float a0 = 0.f, a1 = 0.f, a2 = 0.f, a3 = 0.f;
    int n = s;
    for (; n + 3 < e; n += 4) {
        a0 += h[(size_t)n * D1 + t];
        a1 += h[(size_t)(n + 1) * D1 + t];
        a2 += h[(size_t)(n + 2) * D1 + t];
        a3 += h[(size_t)(n + 3) * D1 + t];
    }
    for (; n < e; n++) a0 += h[(size_t)n * D1 + t];
    float pv = (a0 + a1 + a2 + a3) / fmaxf((float)(e - s), 1.0f);
    float sc = bn3g[t] * rsqrtf(bn3v[t] + 1e-5f);
    z[t] = fmaxf((pv - bn3m[t]) * sc + bn3b[t], 0.f);
    __syncthreads();
    float a = 0.f;
    for (int k = 0; k < 512; k++) a += z[k] * w1[(size_t)k * 512 + t];
    s1[t] = fmaxf(a + b1[t], 0.f);
    __syncthreads();
    if (t < NC * 32) {
        int col = t >> 5, lane = t & 31;
        float sv = 0.f;
        for (int k = lane; k < 512; k += 32) sv += s1[k] * w2[k * NC + col];
#pragma unroll
        for (int o = 16; o; o >>= 1) sv += __shfl_xor_sync(0xffffffffu, sv, o);
        if (!lane) out[g * NC + col] = sv + b2[col];
    }
}

// ---------------- host launcher ----------------
extern "C" void kernel_launch(void* const* d_in, const int* in_sizes, int n_in,
                              void* d_out, int out_size) {
    const float* x        = (const float*)d_in[0];
    const int*   ei       = (const int*)d_in[1];
    const int*   ew       = (const int*)d_in[2];
    const int*   batch    = (const int*)d_in[3];
    const float* mlp_w1   = (const float*)d_in[4];
    const float* mlp_b1   = (const float*)d_in[5];
    const float* bn1_g    = (const float*)d_in[6];
    const float* bn1_b    = (const float*)d_in[7];
    const float* bn1_m    = (const float*)d_in[8];
    const float* bn1_v    = (const float*)d_in[9];
    const float* mlp_w2   = (const float*)d_in[10];
    const float* mlp_b2   = (const float*)d_in[11];
    const float* bn2_g    = (const float*)d_in[12];
    const float* bn2_b    = (const float*)d_in[13];
    const float* bn2_m    = (const float*)d_in[14];
    const float* bn2_v    = (const float*)d_in[15];
    const float* gat0_w   = (const float*)d_in[16];
    const float* gat0_as  = (const float*)d_in[17];
    const float* gat0_ad  = (const float*)d_in[18];
    const float* gat0_bi  = (const float*)d_in[19];
    const float* gat1_w   = (const float*)d_in[20];
    const float* gat1_as  = (const float*)d_in[21];
    const float* gat1_ad  = (const float*)d_in[22];
    const float* gat1_bi  = (const float*)d_in[23];
    const float* bn3_g    = (const float*)d_in[24];
    const float* bn3_b    = (const float*)d_in[25];
    const float* bn3_m    = (const float*)d_in[26];
    const float* bn3_v    = (const float*)d_in[27];
    const float* fin_w1   = (const float*)d_in[28];
    const float* fin_b1   = (const float*)d_in[29];
    const float* fin_w2   = (const float*)d_in[30];
    const float* fin_b2   = (const float*)d_in[31];
    float* out = (float*)d_out;

    float *hp_rx, *hp_h1, *hp_h2, *hp_xw, *hp_h3, *hp_h4;
    float *hp_wt0, *hp_wt1, *hp_wt2, *hp_wt3;
    float *hp_sc1, *hp_sh1, *hp_sc2, *hp_sh2;
    float *hp_ls0, *hp_ld0, *hp_ls1, *hp_ld1;
    cudaGetSymbolAddress((void**)&hp_rx, g_rx);
    cudaGetSymbolAddress((void**)&hp_h1, g_h1);
    cudaGetSymbolAddress((void**)&hp_h2, g_h2);
    cudaGetSymbolAddress((void**)&hp_xw, g_xw);
    cudaGetSymbolAddress((void**)&hp_h3, g_h3);
    cudaGetSymbolAddress((void**)&hp_h4, g_h4);
    cudaGetSymbolAddress((void**)&hp_wt0, g_wt0);
    cudaGetSymbolAddress((void**)&hp_wt1, g_wt1);
    cudaGetSymbolAddress((void**)&hp_wt2, g_wt2);
    cudaGetSymbolAddress((void**)&hp_wt3, g_wt3);
    cudaGetSymbolAddress((void**)&hp_sc1, g_sc1);
    cudaGetSymbolAddress((void**)&hp_sh1, g_sh1);
    cudaGetSymbolAddress((void**)&hp_sc2, g_sc2);
    cudaGetSymbolAddress((void**)&hp_sh2, g_sh2);
    cudaGetSymbolAddress((void**)&hp_ls0, g_ls0);
    cudaGetSymbolAddress((void**)&hp_ld0, g_ld0);
    cudaGetSymbolAddress((void**)&hp_ls1, g_ls1);
    cudaGetSymbolAddress((void**)&hp_ld1, g_ld1);

    cudaFuncSetAttribute(tgemm<0>, cudaFuncAttributeMaxDynamicSharedMemorySize, TG_SMEM);
    cudaFuncSetAttribute(tgemm<1>, cudaFuncAttributeMaxDynamicSharedMemorySize, TG_SMEM);
    cudaFuncSetAttribute(tgemm<2>, cudaFuncAttributeMaxDynamicSharedMemorySize, TG_SMEM);

    // 1) mega-prepass + CSR build
    fused_pre<<<NB_RX + NB_TR, 256>>>(x, batch, ei, ew,
        mlp_b1, bn1_g, bn1_b, bn1_m, bn1_v,
        mlp_b2, bn2_g, bn2_b, bn2_m, bn2_v,
        mlp_w1, mlp_w2, gat0_w, gat1_w);
    scan_blocks<<<(NN + 511) / 512, 512>>>();
    scan_add2<<<(NN + 255) / 256, 256>>>();
    scatter_kernel<<<(EE + 255) / 256, 256>>>(ei, ew);

    const int MB = (NN + 127) / 128;  // 157
    const int AGG_BLOCKS = (NN * 32 + 255) / 256;

    // 2) node MLP (BN=64 tiles)
    tgemm<1><<<dim3(D0 / 64, MB), 256, TG_SMEM>>>(hp_rx, hp_wt0, hp_h1, NN, D0, FF,
        hp_sc1, hp_sh1, nullptr, nullptr, nullptr, nullptr);
    tgemm<1><<<dim3(D0 / 64, MB), 256, TG_SMEM>>>(hp_h1, hp_wt1, hp_h2, NN, D0, D0,
        hp_sc2, hp_sh2, nullptr, nullptr, nullptr, nullptr);

    // 3) GAT layer 0
    tgemm<2><<<dim3(D1 / 64, MB), 256, TG_SMEM>>>(hp_h2, hp_wt2, hp_xw, NN, D1, D0,
        nullptr, nullptr, gat0_as, gat0_ad, hp_ls0, hp_ld0);
    gat_agg<1><<<AGG_BLOCKS, 256>>>(hp_xw, gat0_bi, hp_h3, hp_ls0, hp_ld0);

    // 4) GAT layer 1
    tgemm<2><<<dim3(D1 / 64, MB), 256, TG_SMEM>>>(hp_h3, hp_wt3, hp_xw, NN, D1, D1,
        nullptr, nullptr, gat1_as, gat1_ad, hp_ls1, hp_ld1);
    gat_agg<0><<<AGG_BLOCKS, 256>>>(hp_xw, gat1_bi, hp_h4, hp_ls1, hp_ld1);

    // 5) pooled final head
    final_head<<<GG, 512>>>(hp_h4, bn3_g, bn3_b, bn3_m, bn3_v,
                            fin_w1, fin_b1, fin_w2, fin_b2, out);
}

// round 12
// speedup vs baseline: 1.4580x; 1.0125x over previous
#include <cuda_runtime.h>
#include <cstdint>

#define NN 20000
#define EE 320000
#define FF 128
#define D0 256
#define D1 512
#define HH 2
#define CC 256
#define GG 128
#define NC 10

// ---------------- scratch (device globals; zero-initialized at load) ----------------
__device__ float g_h1[NN * D0];
__device__ float g_h2[NN * D0];
__device__ float g_xw[NN * D1];
__device__ float g_h3[NN * D1];
__device__ float g_h4[NN * D1];
__device__ float g_wt0[FF * D0];
__device__ float g_wt1[D0 * D0];
__device__ float g_wt2[D0 * D1];
__device__ float g_wt3[D1 * D1];
__device__ float g_ls0[NN * HH], g_ld0[NN * HH];
__device__ float g_ls1[NN * HH], g_ld1[NN * HH];
__device__ int   g_deg[NN];      // invariant: all-zero at kernel_launch entry
__device__ int   g_off[NN + 1];
__device__ int   g_cur[NN];
__device__ int   g_csr[EE];
__device__ int   g_bsum[64];
__device__ int   g_goff[GG + 1];
__device__ float g_sc1[D0], g_sh1[D0], g_sc2[D0], g_sh2[D0];

// ---------------- small helpers ----------------
__device__ __forceinline__ float rtf32(float x) {
    uint32_t u;
    asm("cvt.rna.tf32.f32 %0, %1;" : "=r"(u) : "f"(x));
    return __uint_as_float(u);
}
__device__ __forceinline__ uint32_t smem_u32(const void* p) {
    uint32_t a;
    asm("{ .reg .u64 t; cvta.to.shared.u64 t, %1; cvt.u32.u64 %0, t; }" : "=r"(a) : "l"(p));
    return a;
}
__device__ __forceinline__ void cpa16(uint32_t dst, const void* src, int sz) {
    asm volatile("cp.async.cg.shared.global [%0], [%1], 16, %2;"
                 :: "r"(dst), "l"(src), "r"(sz));
}
__device__ __forceinline__ void cp_commit() {
    asm volatile("cp.async.commit_group;");
}
template <int N>
__device__ __forceinline__ void cp_wait() {
    asm volatile("cp.async.wait_group %0;" :: "n"(N));
}
__device__ __forceinline__ void mma_tf32(float* d, const float* a, const float* b) {
    asm volatile(
        "mma.sync.aligned.m16n8k8.row.col.f32.tf32.tf32.f32 "
        "{%0,%1,%2,%3}, {%4,%5,%6,%7}, {%8,%9}, {%0,%1,%2,%3};"
        : "+f"(d[0]), "+f"(d[1]), "+f"(d[2]), "+f"(d[3])
        : "r"(__float_as_uint(a[0])), "r"(__float_as_uint(a[1])),
          "r"(__float_as_uint(a[2])), "r"(__float_as_uint(a[3])),
          "r"(__float_as_uint(b[0])), "r"(__float_as_uint(b[1])));
}

// ---------------- fused prepass: hist + zeros + graph bounds + BN fold + transposes ----------------
#define NB_ED ((EE + 255) / 256)        // 1250
#define NB_TR 480

__global__ void fused_pre(const int* __restrict__ batch,
                          const int* __restrict__ ei, const int* __restrict__ ew,
                          const float* lb1, const float* g1, const float* b1,
                          const float* m1, const float* v1,
                          const float* lb2, const float* g2, const float* b2,
                          const float* m2, const float* v2,
                          const float* __restrict__ w0, const float* __restrict__ w1,
                          const float* __restrict__ w2, const float* __restrict__ w3) {
    if (blockIdx.x >= NB_ED) {
        __shared__ float t[32][33];
        int b = blockIdx.x - NB_ED;
        const float* W; float* Wt; int K, N, bx, by;
        if (b < 32)       { W = w0; Wt = g_wt0; K = FF; N = D0; bx = b % 8;  by = b / 8; }
        else if (b < 96)  { W = w1; Wt = g_wt1; K = D0; N = D0; b -= 32;  bx = b % 8;  by = b / 8; }
        else if (b < 224) { W = w2; Wt = g_wt2; K = D0; N = D1; b -= 96;  bx = b % 16; by = b / 16; }
        else              { W = w3; Wt = g_wt3; K = D1; N = D1; b -= 224; bx = b % 16; by = b / 16; }
        int xx = threadIdx.x & 31, yy = threadIdx.x >> 5;
        int cx = bx * 32, cy = by * 32;
#pragma unroll
        for (int i = 0; i < 32; i += 8)
            t[yy + i][xx] = W[(size_t)(cy + yy + i) * N + cx + xx];
        __syncthreads();
#pragma unroll
        for (int i = 0; i < 32; i += 8)
            Wt[(size_t)(cx + yy + i) * K + cy + xx] = rtf32(t[xx][yy + i]);
        return;
    }
    int i = blockIdx.x * blockDim.x + threadIdx.x;
    if (i < NN * HH) { g_ls0[i] = 0.f; g_ld0[i] = 0.f; g_ls1[i] = 0.f; g_ld1[i] = 0.f; }
    if (i < EE && ew[i] == 1) atomicAdd(&g_deg[ei[EE + i]], 1);
    if (i < NN) {
        if (i == 0) {
            int c = batch[0];
            for (int g = 0; g <= c; g++) g_goff[g] = 0;
        } else {
            int p = batch[i - 1], c = batch[i];
            for (int g = p + 1; g <= c; g++) g_goff[g] = i;
        }
        if (i == NN - 1) {
            int c = batch[NN - 1];
            for (int g = c + 1; g <= GG; g++) g_goff[g] = NN;
        }
    }
    if (blockIdx.x == 0 && threadIdx.x < D0) {
        int t = threadIdx.x;
        float sc = g1[t] * rsqrtf(v1[t] + 1e-5f);
        g_sc1[t] = sc;
        g_sh1[t] = (lb1[t] - m1[t]) * sc + b1[t];
        float sc2 = g2[t] * rsqrtf(v2[t] + 1e-5f);
        g_sc2[t] = sc2;
        g_sh2[t] = (lb2[t] - m2[t]) * sc2 + b2[t];
    }
}

// ---------------- tf32 mma.sync GEMM: CTA 128x64, 8 warps @ 32x32, 4-stage, 3 CTA/SM ----------------
// RNDA==1: round A fragments to tf32 in-register (A read raw from gmem)
#define TG_STAGES 4
#define TG_LDS 20
#define TG_STAGE_FLOATS ((128 + 64) * TG_LDS)       // 3840
#define TG_SMEM (TG_STAGES * TG_STAGE_FLOATS * 4)   // 61440

template <int EPI, int RNDA>
__global__ void __launch_bounds__(256, 3) tgemm(
    const float* __restrict__ A, const float* __restrict__ Bt,
    float* __restrict__ Cm, int M, int Nn, int K,
    const float* __restrict__ scale, const float* __restrict__ shift,
    const float* __restrict__ asrc, const float* __restrict__ adst,
    float* __restrict__ lsb, float* __restrict__ ldb)
{
    extern __shared__ float smem[];
    const int tid = threadIdx.x;
    const int wid = tid >> 5, lane = tid & 31;
    const int wm = wid & 3, wn = wid >> 2;       // 4 m-warps x 2 n-warps
    const int lr = lane >> 2, lc = lane & 3;
    const int m0 = blockIdx.y * 128, n0 = blockIdx.x * 64;

    const int arow = tid >> 1;
    const int ac4 = (tid & 1) * 2;
    const int brow = tid >> 2;
    const int bc4 = tid & 3;
    uint32_t sbase = smem_u32(smem);

    float acc[2][4][4];
#pragma unroll
    for (int i = 0; i < 2; i++)
#pragma unroll
        for (int j = 0; j < 4; j++)
#pragma unroll
            for (int q = 0; q < 4; q++) acc[i][j][q] = 0.f;

    const int nch = K >> 4;

    auto load_chunk = [&](int ch, int st) {
        int k0 = ch << 4;
        uint32_t sA = sbase + (uint32_t)(st * TG_STAGE_FLOATS) * 4u;
        uint32_t sB = sA + (uint32_t)(128 * TG_LDS) * 4u;
        int gr = m0 + arow;
        int ok = (gr < M) ? 16 : 0;
        int grc = (gr < M) ? gr : (M - 1);
#pragma unroll
        for (int i = 0; i < 2; i++) {
            int c4 = ac4 + i;
            cpa16(sA + (uint32_t)(arow * TG_LDS + c4 * 4) * 4u,
                  A + (size_t)grc * K + k0 + c4 * 4, ok);
        }
        cpa16(sB + (uint32_t)(brow * TG_LDS + bc4 * 4) * 4u,
              Bt + (size_t)(n0 + brow) * K + k0 + bc4 * 4, 16);
        cp_commit();
    };

    load_chunk(0, 0);
    if (nch > 1) load_chunk(1, 1);
    if (nch > 2) load_chunk(2, 2);

    for (int ch = 0; ch < nch; ch++) {
        int st = ch % TG_STAGES;
        cp_wait<TG_STAGES - 2>();
        __syncthreads();
        if (ch + 3 < nch) load_chunk(ch + 3, (ch + 3) % TG_STAGES);

        const float* Ab = smem + st * TG_STAGE_FLOATS + (wm * 32 + lr) * TG_LDS + lc;
        const float* Bb = smem + st * TG_STAGE_FLOATS + 128 * TG_LDS + (wn * 32 + lr) * TG_LDS + lc;
#pragma unroll
        for (int ks = 0; ks < 2; ks++) {
            int k0 = ks * 8;
            float a[2][4], b[4][2];
#pragma unroll
            for (int mt = 0; mt < 2; mt++) {
                a[mt][0] = Ab[(mt * 16) * TG_LDS + k0];
                a[mt][1] = Ab[(mt * 16 + 8) * TG_LDS + k0];
                a[mt][2] = Ab[(mt * 16) * TG_LDS + k0 + 4];
                a[mt][3] = Ab[(mt * 16 + 8) * TG_LDS + k0 + 4];
                if (RNDA) {
                    a[mt][0] = rtf32(a[mt][0]);
                    a[mt][1] = rtf32(a[mt][1]);
                    a[mt][2] = rtf32(a[mt][2]);
                    a[mt][3] = rtf32(a[mt][3]);
                }
            }
#pragma unroll
            for (int nt = 0; nt < 4; nt++) {
                b[nt][0] = Bb[(nt * 8) * TG_LDS + k0];
                b[nt][1] = Bb[(nt * 8) * TG_LDS + k0 + 4];
            }
#pragma unroll
            for (int mt = 0; mt < 2; mt++)
#pragma unroll
                for (int nt = 0; nt < 4; nt++)
                    mma_tf32(acc[mt][nt], a[mt], b[nt]);
        }
    }

    // ---- epilogue ----
    float sr[2][2] = {{0.f, 0.f}, {0.f, 0.f}};
    float dr[2][2] = {{0.f, 0.f}, {0.f, 0.f}};
#pragma unroll
    for (int mt = 0; mt < 2; mt++) {
        int row0 = m0 + wm * 32 + mt * 16 + lr;
#pragma unroll
        for (int nt = 0; nt < 4; nt++) {
            int col = n0 + wn * 32 + nt * 8 + lc * 2;
            float v0 = acc[mt][nt][0], v1 = acc[mt][nt][1];
            float v2 = acc[mt][nt][2], v3 = acc[mt][nt][3];
            if (EPI == 1) {
                float s0 = scale[col], s1 = scale[col + 1];
                float h0 = shift[col], h1 = shift[col + 1];
                v0 = rtf32(fmaxf(v0 * s0 + h0, 0.f));
                v1 = rtf32(fmaxf(v1 * s1 + h1, 0.f));
                v2 = rtf32(fmaxf(v2 * s0 + h0, 0.f));
                v3 = rtf32(fmaxf(v3 * s1 + h1, 0.f));
            }
            if (EPI == 2) {
                float as0 = asrc[col], as1 = asrc[col + 1];
                float ad0 = adst[col], ad1 = adst[col + 1];
                sr[mt][0] += v0 * as0 + v1 * as1;
                dr[mt][0] += v0 * ad0 + v1 * ad1;
                sr[mt][1] += v2 * as0 + v3 * as1;
                dr[mt][1] += v2 * ad0 + v3 * ad1;
            }
            if (row0 < M)
                *(float2*)(Cm + (size_t)row0 * Nn + col) = make_float2(v0, v1);
            if (row0 + 8 < M)
                *(float2*)(Cm + (size_t)(row0 + 8) * Nn + col) = make_float2(v2, v3);
        }
    }
    if (EPI == 2) {
        int h = (n0 >= 256) ? 1 : 0;
#pragma unroll
        for (int mt = 0; mt < 2; mt++)
#pragma unroll
            for (int half = 0; half < 2; half++) {
                float s = sr[mt][half], d = dr[mt][half];
                s += __shfl_xor_sync(0xffffffffu, s, 1);
                s += __shfl_xor_sync(0xffffffffu, s, 2);
                d += __shfl_xor_sync(0xffffffffu, d, 1);
                d += __shfl_xor_sync(0xffffffffu, d, 2);
                int row = m0 + wm * 32 + mt * 16 + lr + half * 8;
                if (lc == 0 && row < M) {
                    atomicAdd(&lsb[row * 2 + h], s);
                    atomicAdd(&ldb[row * 2 + h], d);
                }
            }
    }
}

// ---------------- CSR build (K11-identical) ----------------
__global__ void scan_blocks() {
    __shared__ int s[512];
    int tid = threadIdx.x;
    int i = blockIdx.x * 512 + tid;
    int v = (i < NN) ? g_deg[i] : 0;
    if (i < NN) g_deg[i] = 0;
    s[tid] = v;
    __syncthreads();
    for (int off = 1; off < 512; off <<= 1) {
        int u = (tid >= off) ? s[tid - off] : 0;
        __syncthreads();
        s[tid] += u;
        __syncthreads();
    }
    if (i < NN) g_off[i] = s[tid] - v;
    if (tid == 511) g_bsum[blockIdx.x] = s[511];
}

__global__ void scan_add2() {
    __shared__ int base;
    int i = blockIdx.x * blockDim.x + threadIdx.x;
    int sb = (int)((blockIdx.x * blockDim.x) >> 9);
    if (threadIdx.x == 0) {
        int a = 0;
        for (int b = 0; b < sb; b++) a += g_bsum[b];
        base = a;
        if (blockIdx.x == 0) {
            int tot = 0;
            int nblk = (NN + 511) / 512;
            for (int b = 0; b < nblk; b++) tot += g_bsum[b];
            g_off[NN] = tot;
        }
    }
    __syncthreads();
    if (i < NN) {
        int v = g_off[i] + base;
        g_off[i] = v;
        g_cur[i] = v;
    }
}

__global__ void scatter_kernel(const int* __restrict__ ei, const int* __restrict__ ew) {
    int e = blockIdx.x * blockDim.x + threadIdx.x;
    if (e < EE && ew[e] == 1) {
        int d = ei[EE + e];
        int pos = atomicAdd(&g_cur[d], 1);
        g_csr[pos] = ei[e];
    }
}

// ---------------- GAT aggregation: one WARP per node (K11-identical) ----------------
template <int ROUND>
__global__ void __launch_bounds__(256) gat_agg(const float* __restrict__ xw,
                                               const float* __restrict__ bias,
                                               float* __restrict__ out,
                                               const float* __restrict__ lsb,
                                               const float* __restrict__ ldb) {
    int gw = (blockIdx.x * blockDim.x + threadIdx.x) >> 5;
    if (gw >= NN) return;
    int lane = threadIdx.x & 31;
    int n = gw;
    int beg = g_off[n], end = g_off[n + 1];
    int deg = end - beg;
    float ld0 = ldb[n * 2], ld1 = ldb[n * 2 + 1];

    float4 a0 = make_float4(0.f, 0.f, 0.f, 0.f);
    float4 a1 = a0, a2 = a0, a3 = a0;
    float den0 = 0.f, den1 = 0.f;

#define ACC_EDGE(SL, P0V, P1V, J)                                               \
    {                                                                           \
        int s_ = __shfl_sync(0xffffffffu, (SL), (J));                           \
        float q0_ = __shfl_sync(0xffffffffu, (P0V), (J));                       \
        float q1_ = __shfl_sync(0xffffffffu, (P1V), (J));                       \
        const float4* row_ = (const float4*)(xw + (size_t)s_ * D1);             \
        float4 v0_ = row_[lane];                                                \
        float4 v1_ = row_[32 + lane];                                           \
        float4 v2_ = row_[64 + lane];                                           \
        float4 v3_ = row_[96 + lane];                                           \
        a0.x += q0_ * v0_.x; a0.y += q0_ * v0_.y; a0.z += q0_ * v0_.z; a0.w += q0_ * v0_.w; \
        a1.x += q0_ * v1_.x; a1.y += q0_ * v1_.y; a1.z += q0_ * v1_.z; a1.w += q0_ * v1_.w; \
        a2.x += q1_ * v2_.x; a2.y += q1_ * v2_.y; a2.z += q1_ * v2_.z; a2.w += q1_ * v2_.w; \
        a3.x += q1_ * v3_.x; a3.y += q1_ * v3_.y; a3.z += q1_ * v3_.z; a3.w += q1_ * v3_.w; \
    }

    if (deg <= 32) {
        int sl = 0;
        float e0 = -1e30f, e1 = -1e30f;
        if (lane < deg) {
            sl = g_csr[beg + lane];
            e0 = lsb[sl * 2] + ld0;     e0 = e0 > 0.f ? e0 : 0.2f * e0;
            e1 = lsb[sl * 2 + 1] + ld1; e1 = e1 > 0.f ? e1 : 0.2f * e1;
        }
        float m0 = e0, m1 = e1;
#pragma unroll
        for (int o = 16; o; o >>= 1) {
            m0 = fmaxf(m0, __shfl_xor_sync(0xffffffffu, m0, o));
            m1 = fmaxf(m1, __shfl_xor_sync(0xffffffffu, m1, o));
        }
        float p0 = (lane < deg) ? __expf(e0 - m0) : 0.f;
        float p1 = (lane < deg) ? __expf(e1 - m1) : 0.f;
        den0 = p0; den1 = p1;
        int j = 0;
        for (; j + 1 < deg; j += 2) { ACC_EDGE(sl, p0, p1, j); ACC_EDGE(sl, p0, p1, j + 1); }
        if (j < deg) ACC_EDGE(sl, p0, p1, j);
    } else {
        float m0 = -1e30f, m1 = -1e30f;
        for (int i = lane; i < deg; i += 32) {
            int s = g_csr[beg + i];
            float e0 = lsb[s * 2] + ld0;     e0 = e0 > 0.f ? e0 : 0.2f * e0;
            float e1 = lsb[s * 2 + 1] + ld1; e1 = e1 > 0.f ? e1 : 0.2f * e1;
            m0 = fmaxf(m0, e0);
            m1 = fmaxf(m1, e1);
        }
#pragma unroll
        for (int o = 16; o; o >>= 1) {
            m0 = fmaxf(m0, __shfl_xor_sync(0xffffffffu, m0, o));
            m1 = fmaxf(m1, __shfl_xor_sync(0xffffffffu, m1, o));
        }
        for (int base = 0; base < deg; base += 32) {
            int i = base + lane;
            float p0 = 0.f, p1 = 0.f;
            int sl = 0;
            if (i < deg) {
                sl = g_csr[beg + i];
                float e0 = lsb[sl * 2] + ld0;     e0 = e0 > 0.f ? e0 : 0.2f * e0;
                float e1 = lsb[sl * 2 + 1] + ld1; e1 = e1 > 0.f ? e1 : 0.2f * e1;
                p0 = __expf(e0 - m0);
                p1 = __expf(e1 - m1);
            }
            den0 += p0; den1 += p1;
            int cnt = min(32, deg - base);
            int j = 0;
            for (; j + 1 < cnt; j += 2) { ACC_EDGE(sl, p0, p1, j); ACC_EDGE(sl, p0, p1, j + 1); }
            if (j < cnt) ACC_EDGE(sl, p0, p1, j);
        }
    }
#undef ACC_EDGE

#pragma unroll
    for (int o = 16; o; o >>= 1) {
        den0 += __shfl_xor_sync(0xffffffffu, den0, o);
        den1 += __shfl_xor_sync(0xffffffffu, den1, o);
    }
    float r0 = 1.f / (den0 + 1e-16f), r1 = 1.f / (den1 + 1e-16f);

    const float4* bi = (const float4*)bias;
    float4* op = (float4*)(out + (size_t)n * D1);
    float4 b0 = bi[lane], b1 = bi[32 + lane], b2 = bi[64 + lane], b3 = bi[96 + lane];
    float4 o0 = make_float4(a0.x * r0 + b0.x, a0.y * r0 + b0.y, a0.z * r0 + b0.z, a0.w * r0 + b0.w);
    float4 o1 = make_float4(a1.x * r0 + b1.x, a1.y * r0 + b1.y, a1.z * r0 + b1.z, a1.w * r0 + b1.w);
    float4 o2 = make_float4(a2.x * r1 + b2.x, a2.y * r1 + b2.y, a2.z * r1 + b2.z, a2.w * r1 + b2.w);
    float4 o3 = make_float4(a3.x * r1 + b3.x, a3.y * r1 + b3.y, a3.z * r1 + b3.z, a3.w * r1 + b3.w);
    if (ROUND) {
        o0 = make_float4(rtf32(o0.x), rtf32(o0.y), rtf32(o0.z), rtf32(o0.w));
        o1 = make_float4(rtf32(o1.x), rtf32(o1.y), rtf32(o1.z), rtf32(o1.w));
        o2 = make_float4(rtf32(o2.x), rtf32(o2.y), rtf32(o2.z), rtf32(o2.w));
        o3 = make_float4(rtf32(o3.x), rtf32(o3.y), rtf32(o3.z), rtf32(o3.w));
    }
    op[lane] = o0;
    op[32 + lane] = o1;
    op[64 + lane] = o2;
    op[96 + lane] = o3;
}

// ---------------- final head (K11-identical: 128 blocks, pooling fused) ----------------
__global__ void __launch_bounds__(512) final_head(
    const float* __restrict__ h,
    const float* __restrict__ bn3g, const float* __restrict__ bn3b,
    const float* __restrict__ bn3m, const float* __restrict__ bn3v,
    const float* __restrict__ w1, const float* __restrict__ b1,
    const float* __restrict__ w2, const float* __restrict__ b2,
    float* __restrict__ out)
{
    int g = blockIdx.x, t = threadIdx.x;
    __shared__ float z[512];
    __shared__ float s1[512];
    int s = g_goff[g], e = g_goff[g + 1];
    float a0 = 0.f, a1 = 0.f, a2 = 0.f, a3 = 0.f;
    int n = s;
    for (; n + 3 < e; n += 4) {
        a0 += h[(size_t)n * D1 + t];
        a1 += h[(size_t)(n + 1) * D1 + t];
        a2 += h[(size_t)(n + 2) * D1 + t];
        a3 += h[(size_t)(n + 3) * D1 + t];
    }
    for (; n < e; n++) a0 += h[(size_t)n * D1 + t];
    float pv = (a0 + a1 + a2 + a3) / fmaxf((float)(e - s), 1.0f);
    float sc = bn3g[t] * rsqrtf(bn3v[t] + 1e-5f);
    z[t] = fmaxf((pv - bn3m[t]) * sc + bn3b[t], 0.f);
    __syncthreads();
    float a = 0.f;
    for (int k = 0; k < 512; k++) a += z[k] * w1[(size_t)k * 512 + t];
    s1[t] = fmaxf(a + b1[t], 0.f);
    __syncthreads();
    if (t < NC * 32) {
        int col = t >> 5, lane = t & 31;
        float sv = 0.f;
        for (int k = lane; k < 512; k += 32) sv += s1[k] * w2[k * NC + col];
#pragma unroll
        for (int o = 16; o; o >>= 1) sv += __shfl_xor_sync(0xffffffffu, sv, o);
        if (!lane) out[g * NC + col] = sv + b2[col];
    }
}

// ---------------- host launcher ----------------
extern "C" void kernel_launch(void* const* d_in, const int* in_sizes, int n_in,
                              void* d_out, int out_size) {
    const float* x        = (const float*)d_in[0];
    const int*   ei       = (const int*)d_in[1];
    const int*   ew       = (const int*)d_in[2];
    const int*   batch    = (const int*)d_in[3];
    const float* mlp_w1   = (const float*)d_in[4];
    const float* mlp_b1   = (const float*)d_in[5];
    const float* bn1_g    = (const float*)d_in[6];
    const float* bn1_b    = (const float*)d_in[7];
    const float* bn1_m    = (const float*)d_in[8];
    const float* bn1_v    = (const float*)d_in[9];
    const float* mlp_w2   = (const float*)d_in[10];
    const float* mlp_b2   = (const float*)d_in[11];
    const float* bn2_g    = (const float*)d_in[12];
    const float* bn2_b    = (const float*)d_in[13];
    const float* bn2_m    = (const float*)d_in[14];
    const float* bn2_v    = (const float*)d_in[15];
    const float* gat0_w   = (const float*)d_in[16];
    const float* gat0_as  = (const float*)d_in[17];
    const float* gat0_ad  = (const float*)d_in[18];
    const float* gat0_bi  = (const float*)d_in[19];
    const float* gat1_w   = (const float*)d_in[20];
    const float* gat1_as  = (const float*)d_in[21];
    const float* gat1_ad  = (const float*)d_in[22];
    const float* gat1_bi  = (const float*)d_in[23];
    const float* bn3_g    = (const float*)d_in[24];
    const float* bn3_b    = (const float*)d_in[25];
    const float* bn3_m    = (const float*)d_in[26];
    const float* bn3_v    = (const float*)d_in[27];
    const float* fin_w1   = (const float*)d_in[28];
    const float* fin_b1   = (const float*)d_in[29];
    const float* fin_w2   = (const float*)d_in[30];
    const float* fin_b2   = (const float*)d_in[31];
    float* out = (float*)d_out;

    float *hp_h1, *hp_h2, *hp_xw, *hp_h3, *hp_h4;
    float *hp_wt0, *hp_wt1, *hp_wt2, *hp_wt3;
    float *hp_sc1, *hp_sh1, *hp_sc2, *hp_sh2;
    float *hp_ls0, *hp_ld0, *hp_ls1, *hp_ld1;
    cudaGetSymbolAddress((void**)&hp_h1, g_h1);
    cudaGetSymbolAddress((void**)&hp_h2, g_h2);
    cudaGetSymbolAddress((void**)&hp_xw, g_xw);
    cudaGetSymbolAddress((void**)&hp_h3, g_h3);
    cudaGetSymbolAddress((void**)&hp_h4, g_h4);
    cudaGetSymbolAddress((void**)&hp_wt0, g_wt0);
    cudaGetSymbolAddress((void**)&hp_wt1, g_wt1);
    cudaGetSymbolAddress((void**)&hp_wt2, g_wt2);
    cudaGetSymbolAddress((void**)&hp_wt3, g_wt3);
    cudaGetSymbolAddress((void**)&hp_sc1, g_sc1);
    cudaGetSymbolAddress((void**)&hp_sh1, g_sh1);
    cudaGetSymbolAddress((void**)&hp_sc2, g_sc2);
    cudaGetSymbolAddress((void**)&hp_sh2, g_sh2);
    cudaGetSymbolAddress((void**)&hp_ls0, g_ls0);
    cudaGetSymbolAddress((void**)&hp_ld0, g_ld0);
    cudaGetSymbolAddress((void**)&hp_ls1, g_ls1);
    cudaGetSymbolAddress((void**)&hp_ld1, g_ld1);

    cudaFuncSetAttribute((const void*)tgemm<1, 1>, cudaFuncAttributeMaxDynamicSharedMemorySize, TG_SMEM);
    cudaFuncSetAttribute((const void*)tgemm<1, 0>, cudaFuncAttributeMaxDynamicSharedMemorySize, TG_SMEM);
    cudaFuncSetAttribute((const void*)tgemm<2, 0>, cudaFuncAttributeMaxDynamicSharedMemorySize, TG_SMEM);

    // 1) prepass (hist + zeros + bounds + BN fold + transposes) + CSR
    fused_pre<<<NB_ED + NB_TR, 256>>>(batch, ei, ew,
        mlp_b1, bn1_g, bn1_b, bn1_m, bn1_v,
        mlp_b2, bn2_g, bn2_b, bn2_m, bn2_v,
        mlp_w1, mlp_w2, gat0_w, gat1_w);
    scan_blocks<<<(NN + 511) / 512, 512>>>();
    scan_add2<<<(NN + 255) / 256, 256>>>();
    scatter_kernel<<<(EE + 255) / 256, 256>>>(ei, ew);

    const int MB = (NN + 127) / 128;  // 157
    const int AGG_BLOCKS = (NN * 32 + 255) / 256;

    // 2) node MLP (GEMM1 reads raw x, rounds A in-register; BN=64 tiles)
    tgemm<1, 1><<<dim3(D0 / 64, MB), 256, TG_SMEM>>>(x, hp_wt0, hp_h1, NN, D0, FF,
        hp_sc1, hp_sh1, nullptr, nullptr, nullptr, nullptr);
    tgemm<1, 0><<<dim3(D0 / 64, MB), 256, TG_SMEM>>>(hp_h1, hp_wt1, hp_h2, NN, D0, D0,
        hp_sc2, hp_sh2, nullptr, nullptr, nullptr, nullptr);

    // 3) GAT layer 0
    tgemm<2, 0><<<dim3(D1 / 64, MB), 256, TG_SMEM>>>(hp_h2, hp_wt2, hp_xw, NN, D1, D0,
        nullptr, nullptr, gat0_as, gat0_ad, hp_ls0, hp_ld0);
    gat_agg<1><<<AGG_BLOCKS, 256>>>(hp_xw, gat0_bi, hp_h3, hp_ls0, hp_ld0);

    // 4) GAT layer 1
    tgemm<2, 0><<<dim3(D1 / 64, MB), 256, TG_SMEM>>>(hp_h3, hp_wt3, hp_xw, NN, D1, D1,
        nullptr, nullptr, gat1_as, gat1_ad, hp_ls1, hp_ld1);
    gat_agg<0><<<AGG_BLOCKS, 256>>>(hp_xw, gat1_bi, hp_h4, hp_ls1, hp_ld1);

    // 5) pooled final head
    final_head<<<GG, 512>>>(hp_h4, bn3_g, bn3_b, bn3_m, bn3_v,
                            fin_w1, fin_b1, fin_w2, fin_b2, out);
}

// round 13
// speedup vs baseline: 1.4848x; 1.0184x over previous
#include <cuda_runtime.h>
#include <cstdint>

#define NN 20000
#define EE 320000
#define FF 128
#define D0 256
#define D1 512
#define HH 2
#define CC 256
#define GG 128
#define NC 10

// ---------------- scratch (device globals; zero-initialized at load) ----------------
__device__ float g_h1[NN * D0];
__device__ float g_h2[NN * D0];
__device__ float g_xw[NN * D1];
__device__ float g_h3[NN * D1];
__device__ float g_h4[NN * D1];
__device__ float g_wt0[FF * D0];
__device__ float g_wt1[D0 * D0];
__device__ float g_wt2[D0 * D1];
__device__ float g_wt3[D1 * D1];
__device__ float g_ls0[NN * HH], g_ld0[NN * HH];
__device__ float g_ls1[NN * HH], g_ld1[NN * HH];
__device__ int   g_deg[NN];      // invariant: all-zero at kernel_launch entry
__device__ int   g_off[NN + 1];
__device__ int   g_cur[NN];
__device__ int   g_csr[EE];
__device__ int   g_bsum[64];
__device__ int   g_goff[GG + 1];
__device__ float g_sc1[D0], g_sh1[D0], g_sc2[D0], g_sh2[D0];

// ---------------- small helpers ----------------
__device__ __forceinline__ float rtf32(float x) {
    uint32_t u;
    asm("cvt.rna.tf32.f32 %0, %1;" : "=r"(u) : "f"(x));
    return __uint_as_float(u);
}
__device__ __forceinline__ uint32_t smem_u32(const void* p) {
    uint32_t a;
    asm("{ .reg .u64 t; cvta.to.shared.u64 t, %1; cvt.u32.u64 %0, t; }" : "=r"(a) : "l"(p));
    return a;
}
__device__ __forceinline__ void cpa16(uint32_t dst, const void* src, int sz) {
    asm volatile("cp.async.cg.shared.global [%0], [%1], 16, %2;"
                 :: "r"(dst), "l"(src), "r"(sz));
}
__device__ __forceinline__ void cp_commit() {
    asm volatile("cp.async.commit_group;");
}
template <int N>
__device__ __forceinline__ void cp_wait() {
    asm volatile("cp.async.wait_group %0;" :: "n"(N));
}
__device__ __forceinline__ void mma_tf32(float* d, const float* a, const float* b) {
    asm volatile(
        "mma.sync.aligned.m16n8k8.row.col.f32.tf32.tf32.f32 "
        "{%0,%1,%2,%3}, {%4,%5,%6,%7}, {%8,%9}, {%0,%1,%2,%3};"
        : "+f"(d[0]), "+f"(d[1]), "+f"(d[2]), "+f"(d[3])
        : "r"(__float_as_uint(a[0])), "r"(__float_as_uint(a[1])),
          "r"(__float_as_uint(a[2])), "r"(__float_as_uint(a[3])),
          "r"(__float_as_uint(b[0])), "r"(__float_as_uint(b[1])));
}

// ---------------- fused prepass: hist + zeros + graph bounds + BN fold + transposes ----------------
#define NB_ED ((EE + 255) / 256)        // 1250
#define NB_TR 480

__global__ void fused_pre(const int* __restrict__ batch,
                          const int* __restrict__ ei, const int* __restrict__ ew,
                          const float* lb1, const float* g1, const float* b1,
                          const float* m1, const float* v1,
                          const float* lb2, const float* g2, const float* b2,
                          const float* m2, const float* v2,
                          const float* __restrict__ w0, const float* __restrict__ w1,
                          const float* __restrict__ w2, const float* __restrict__ w3) {
    if (blockIdx.x >= NB_ED) {
        __shared__ float t[32][33];
        int b = blockIdx.x - NB_ED;
        const float* W; float* Wt; int K, N, bx, by;
        if (b < 32)       { W = w0; Wt = g_wt0; K = FF; N = D0; bx = b % 8;  by = b / 8; }
        else if (b < 96)  { W = w1; Wt = g_wt1; K = D0; N = D0; b -= 32;  bx = b % 8;  by = b / 8; }
        else if (b < 224) { W = w2; Wt = g_wt2; K = D0; N = D1; b -= 96;  bx = b % 16; by = b / 16; }
        else              { W = w3; Wt = g_wt3; K = D1; N = D1; b -= 224; bx = b % 16; by = b / 16; }
        int xx = threadIdx.x & 31, yy = threadIdx.x >> 5;
        int cx = bx * 32, cy = by * 32;
#pragma unroll
        for (int i = 0; i < 32; i += 8)
            t[yy + i][xx] = W[(size_t)(cy + yy + i) * N + cx + xx];
        __syncthreads();
#pragma unroll
        for (int i = 0; i < 32; i += 8)
            Wt[(size_t)(cx + yy + i) * K + cy + xx] = rtf32(t[xx][yy + i]);
        return;
    }
    int i = blockIdx.x * blockDim.x + threadIdx.x;
    if (i < NN * HH) { g_ls0[i] = 0.f; g_ld0[i] = 0.f; g_ls1[i] = 0.f; g_ld1[i] = 0.f; }
    if (i < EE && ew[i] == 1) atomicAdd(&g_deg[ei[EE + i]], 1);
    if (i < NN) {
        if (i == 0) {
            int c = batch[0];
            for (int g = 0; g <= c; g++) g_goff[g] = 0;
        } else {
            int p = batch[i - 1], c = batch[i];
            for (int g = p + 1; g <= c; g++) g_goff[g] = i;
        }
        if (i == NN - 1) {
            int c = batch[NN - 1];
            for (int g = c + 1; g <= GG; g++) g_goff[g] = NN;
        }
    }
    if (blockIdx.x == 0 && threadIdx.x < D0) {
        int t = threadIdx.x;
        float sc = g1[t] * rsqrtf(v1[t] + 1e-5f);
        g_sc1[t] = sc;
        g_sh1[t] = (lb1[t] - m1[t]) * sc + b1[t];
        float sc2 = g2[t] * rsqrtf(v2[t] + 1e-5f);
        g_sc2[t] = sc2;
        g_sh2[t] = (lb2[t] - m2[t]) * sc2 + b2[t];
    }
}

// ---------------- tf32 mma.sync GEMM: CTA 128x64, 8 warps @ 32x32, 4-stage, 3 CTA/SM ----------------
// RNDA==1: round A fragments to tf32 in-register (A read raw from gmem)
#define TG_STAGES 4
#define TG_LDS 20
#define TG_STAGE_FLOATS ((128 + 64) * TG_LDS)       // 3840
#define TG_SMEM (TG_STAGES * TG_STAGE_FLOATS * 4)   // 61440

template <int EPI, int RNDA>
__global__ void __launch_bounds__(256, 3) tgemm(
    const float* __restrict__ A, const float* __restrict__ Bt,
    float* __restrict__ Cm, int M, int Nn, int K,
    const float* __restrict__ scale, const float* __restrict__ shift,
    const float* __restrict__ asrc, const float* __restrict__ adst,
    float* __restrict__ lsb, float* __restrict__ ldb)
{
    extern __shared__ float smem[];
    const int tid = threadIdx.x;
    const int wid = tid >> 5, lane = tid & 31;
    const int wm = wid & 3, wn = wid >> 2;       // 4 m-warps x 2 n-warps
    const int lr = lane >> 2, lc = lane & 3;
    const int m0 = blockIdx.y * 128, n0 = blockIdx.x * 64;

    const int arow = tid >> 1;
    const int ac4 = (tid & 1) * 2;
    const int brow = tid >> 2;
    const int bc4 = tid & 3;
    uint32_t sbase = smem_u32(smem);

    float acc[2][4][4];
#pragma unroll
    for (int i = 0; i < 2; i++)
#pragma unroll
        for (int j = 0; j < 4; j++)
#pragma unroll
            for (int q = 0; q < 4; q++) acc[i][j][q] = 0.f;

    const int nch = K >> 4;

    auto load_chunk = [&](int ch, int st) {
        int k0 = ch << 4;
        uint32_t sA = sbase + (uint32_t)(st * TG_STAGE_FLOATS) * 4u;
        uint32_t sB = sA + (uint32_t)(128 * TG_LDS) * 4u;
        int gr = m0 + arow;
        int ok = (gr < M) ? 16 : 0;
        int grc = (gr < M) ? gr : (M - 1);
#pragma unroll
        for (int i = 0; i < 2; i++) {
            int c4 = ac4 + i;
            cpa16(sA + (uint32_t)(arow * TG_LDS + c4 * 4) * 4u,
                  A + (size_t)grc * K + k0 + c4 * 4, ok);
        }
        cpa16(sB + (uint32_t)(brow * TG_LDS + bc4 * 4) * 4u,
              Bt + (size_t)(n0 + brow) * K + k0 + bc4 * 4, 16);
        cp_commit();
    };

    load_chunk(0, 0);
    if (nch > 1) load_chunk(1, 1);
    if (nch > 2) load_chunk(2, 2);

    for (int ch = 0; ch < nch; ch++) {
        int st = ch % TG_STAGES;
        cp_wait<TG_STAGES - 2>();
        __syncthreads();
        if (ch + 3 < nch) load_chunk(ch + 3, (ch + 3) % TG_STAGES);

        const float* Ab = smem + st * TG_STAGE_FLOATS + (wm * 32 + lr) * TG_LDS + lc;
        const float* Bb = smem + st * TG_STAGE_FLOATS + 128 * TG_LDS + (wn * 32 + lr) * TG_LDS + lc;
#pragma unroll
        for (int ks = 0; ks < 2; ks++) {
            int k0 = ks * 8;
            float a[2][4], b[4][2];
#pragma unroll
            for (int mt = 0; mt < 2; mt++) {
                a[mt][0] = Ab[(mt * 16) * TG_LDS + k0];
                a[mt][1] = Ab[(mt * 16 + 8) * TG_LDS + k0];
                a[mt][2] = Ab[(mt * 16) * TG_LDS + k0 + 4];
                a[mt][3] = Ab[(mt * 16 + 8) * TG_LDS + k0 + 4];
                if (RNDA) {
                    a[mt][0] = rtf32(a[mt][0]);
                    a[mt][1] = rtf32(a[mt][1]);
                    a[mt][2] = rtf32(a[mt][2]);
                    a[mt][3] = rtf32(a[mt][3]);
                }
            }
#pragma unroll
            for (int nt = 0; nt < 4; nt++) {
                b[nt][0] = Bb[(nt * 8) * TG_LDS + k0];
                b[nt][1] = Bb[(nt * 8) * TG_LDS + k0 + 4];
            }
#pragma unroll
            for (int mt = 0; mt < 2; mt++)
#pragma unroll
                for (int nt = 0; nt < 4; nt++)
                    mma_tf32(acc[mt][nt], a[mt], b[nt]);
        }
    }

    // ---- epilogue ----
    float sr[2][2] = {{0.f, 0.f}, {0.f, 0.f}};
    float dr[2][2] = {{0.f, 0.f}, {0.f, 0.f}};
#pragma unroll
    for (int mt = 0; mt < 2; mt++) {
        int row0 = m0 + wm * 32 + mt * 16 + lr;
#pragma unroll
        for (int nt = 0; nt < 4; nt++) {
            int col = n0 + wn * 32 + nt * 8 + lc * 2;
            float v0 = acc[mt][nt][0], v1 = acc[mt][nt][1];
            float v2 = acc[mt][nt][2], v3 = acc[mt][nt][3];
            if (EPI == 1) {
                float s0 = scale[col], s1 = scale[col + 1];
                float h0 = shift[col], h1 = shift[col + 1];
                v0 = rtf32(fmaxf(v0 * s0 + h0, 0.f));
                v1 = rtf32(fmaxf(v1 * s1 + h1, 0.f));
                v2 = rtf32(fmaxf(v2 * s0 + h0, 0.f));
                v3 = rtf32(fmaxf(v3 * s1 + h1, 0.f));
            }
            if (EPI == 2) {
                float as0 = asrc[col], as1 = asrc[col + 1];
                float ad0 = adst[col], ad1 = adst[col + 1];
                sr[mt][0] += v0 * as0 + v1 * as1;
                dr[mt][0] += v0 * ad0 + v1 * ad1;
                sr[mt][1] += v2 * as0 + v3 * as1;
                dr[mt][1] += v2 * ad0 + v3 * ad1;
            }
            if (row0 < M)
                *(float2*)(Cm + (size_t)row0 * Nn + col) = make_float2(v0, v1);
            if (row0 + 8 < M)
                *(float2*)(Cm + (size_t)(row0 + 8) * Nn + col) = make_float2(v2, v3);
        }
    }
    if (EPI == 2) {
        int h = (n0 >= 256) ? 1 : 0;
#pragma unroll
        for (int mt = 0; mt < 2; mt++)
#pragma unroll
            for (int half = 0; half < 2; half++) {
                float s = sr[mt][half], d = dr[mt][half];
                s += __shfl_xor_sync(0xffffffffu, s, 1);
                s += __shfl_xor_sync(0xffffffffu, s, 2);
                d += __shfl_xor_sync(0xffffffffu, d, 1);
                d += __shfl_xor_sync(0xffffffffu, d, 2);
                int row = m0 + wm * 32 + mt * 16 + lr + half * 8;
                if (lc == 0 && row < M) {
                    atomicAdd(&lsb[row * 2 + h], s);
                    atomicAdd(&ldb[row * 2 + h], d);
                }
            }
    }
}

// ---------------- CSR build (K12-identical kernels) ----------------
__global__ void scan_blocks() {
    __shared__ int s[512];
    int tid = threadIdx.x;
    int i = blockIdx.x * 512 + tid;
    int v = (i < NN) ? g_deg[i] : 0;
    if (i < NN) g_deg[i] = 0;
    s[tid] = v;
    __syncthreads();
    for (int off = 1; off < 512; off <<= 1) {
        int u = (tid >= off) ? s[tid - off] : 0;
        __syncthreads();
        s[tid] += u;
        __syncthreads();
    }
    if (i < NN) g_off[i] = s[tid] - v;
    if (tid == 511) g_bsum[blockIdx.x] = s[511];
}

__global__ void scan_add2() {
    __shared__ int base;
    int i = blockIdx.x * blockDim.x + threadIdx.x;
    int sb = (int)((blockIdx.x * blockDim.x) >> 9);
    if (threadIdx.x == 0) {
        int a = 0;
        for (int b = 0; b < sb; b++) a += g_bsum[b];
        base = a;
        if (blockIdx.x == 0) {
            int tot = 0;
            int nblk = (NN + 511) / 512;
            for (int b = 0; b < nblk; b++) tot += g_bsum[b];
            g_off[NN] = tot;
        }
    }
    __syncthreads();
    if (i < NN) {
        int v = g_off[i] + base;
        g_off[i] = v;
        g_cur[i] = v;
    }
}

__global__ void scatter_kernel(const int* __restrict__ ei, const int* __restrict__ ew) {
    int e = blockIdx.x * blockDim.x + threadIdx.x;
    if (e < EE && ew[e] == 1) {
        int d = ei[EE + e];
        int pos = atomicAdd(&g_cur[d], 1);
        g_csr[pos] = ei[e];
    }
}

// ---------------- GAT aggregation: one WARP per node (K12-identical) ----------------
template <int ROUND>
__global__ void __launch_bounds__(256) gat_agg(const float* __restrict__ xw,
                                               const float* __restrict__ bias,
                                               float* __restrict__ out,
                                               const float* __restrict__ lsb,
                                               const float* __restrict__ ldb) {
    int gw = (blockIdx.x * blockDim.x + threadIdx.x) >> 5;
    if (gw >= NN) return;
    int lane = threadIdx.x & 31;
    int n = gw;
    int beg = g_off[n], end = g_off[n + 1];
    int deg = end - beg;
    float ld0 = ldb[n * 2], ld1 = ldb[n * 2 + 1];

    float4 a0 = make_float4(0.f, 0.f, 0.f, 0.f);
    float4 a1 = a0, a2 = a0, a3 = a0;
    float den0 = 0.f, den1 = 0.f;

#define ACC_EDGE(SL, P0V, P1V, J)                                               \
    {                                                                           \
        int s_ = __shfl_sync(0xffffffffu, (SL), (J));                           \
        float q0_ = __shfl_sync(0xffffffffu, (P0V), (J));                       \
        float q1_ = __shfl_sync(0xffffffffu, (P1V), (J));                       \
        const float4* row_ = (const float4*)(xw + (size_t)s_ * D1);             \
        float4 v0_ = row_[lane];                                                \
        float4 v1_ = row_[32 + lane];                                           \
        float4 v2_ = row_[64 + lane];                                           \
        float4 v3_ = row_[96 + lane];                                           \
        a0.x += q0_ * v0_.x; a0.y += q0_ * v0_.y; a0.z += q0_ * v0_.z; a0.w += q0_ * v0_.w; \
        a1.x += q0_ * v1_.x; a1.y += q0_ * v1_.y; a1.z += q0_ * v1_.z; a1.w += q0_ * v1_.w; \
        a2.x += q1_ * v2_.x; a2.y += q1_ * v2_.y; a2.z += q1_ * v2_.z; a2.w += q1_ * v2_.w; \
        a3.x += q1_ * v3_.x; a3.y += q1_ * v3_.y; a3.z += q1_ * v3_.z; a3.w += q1_ * v3_.w; \
    }

    if (deg <= 32) {
        int sl = 0;
        float e0 = -1e30f, e1 = -1e30f;
        if (lane < deg) {
            sl = g_csr[beg + lane];
            e0 = lsb[sl * 2] + ld0;     e0 = e0 > 0.f ? e0 : 0.2f * e0;
            e1 = lsb[sl * 2 + 1] + ld1; e1 = e1 > 0.f ? e1 : 0.2f * e1;
        }
        float m0 = e0, m1 = e1;
#pragma unroll
        for (int o = 16; o; o >>= 1) {
            m0 = fmaxf(m0, __shfl_xor_sync(0xffffffffu, m0, o));
            m1 = fmaxf(m1, __shfl_xor_sync(0xffffffffu, m1, o));
        }
        float p0 = (lane < deg) ? __expf(e0 - m0) : 0.f;
        float p1 = (lane < deg) ? __expf(e1 - m1) : 0.f;
        den0 = p0; den1 = p1;
        int j = 0;
        for (; j + 1 < deg; j += 2) { ACC_EDGE(sl, p0, p1, j); ACC_EDGE(sl, p0, p1, j + 1); }
        if (j < deg) ACC_EDGE(sl, p0, p1, j);
    } else {
        float m0 = -1e30f, m1 = -1e30f;
        for (int i = lane; i < deg; i += 32) {
            int s = g_csr[beg + i];
            float e0 = lsb[s * 2] + ld0;     e0 = e0 > 0.f ? e0 : 0.2f * e0;
            float e1 = lsb[s * 2 + 1] + ld1; e1 = e1 > 0.f ? e1 : 0.2f * e1;
            m0 = fmaxf(m0, e0);
            m1 = fmaxf(m1, e1);
        }
#pragma unroll
        for (int o = 16; o; o >>= 1) {
            m0 = fmaxf(m0, __shfl_xor_sync(0xffffffffu, m0, o));
            m1 = fmaxf(m1, __shfl_xor_sync(0xffffffffu, m1, o));
        }
        for (int base = 0; base < deg; base += 32) {
            int i = base + lane;
            float p0 = 0.f, p1 = 0.f;
            int sl = 0;
            if (i < deg) {
                sl = g_csr[beg + i];
                float e0 = lsb[sl * 2] + ld0;     e0 = e0 > 0.f ? e0 : 0.2f * e0;
                float e1 = lsb[sl * 2 + 1] + ld1; e1 = e1 > 0.f ? e1 : 0.2f * e1;
                p0 = __expf(e0 - m0);
                p1 = __expf(e1 - m1);
            }
            den0 += p0; den1 += p1;
            int cnt = min(32, deg - base);
            int j = 0;
            for (; j + 1 < cnt; j += 2) { ACC_EDGE(sl, p0, p1, j); ACC_EDGE(sl, p0, p1, j + 1); }
            if (j < cnt) ACC_EDGE(sl, p0, p1, j);
        }
    }
#undef ACC_EDGE

#pragma unroll
    for (int o = 16; o; o >>= 1) {
        den0 += __shfl_xor_sync(0xffffffffu, den0, o);
        den1 += __shfl_xor_sync(0xffffffffu, den1, o);
    }
    float r0 = 1.f / (den0 + 1e-16f), r1 = 1.f / (den1 + 1e-16f);

    const float4* bi = (const float4*)bias;
    float4* op = (float4*)(out + (size_t)n * D1);
    float4 b0 = bi[lane], b1 = bi[32 + lane], b2 = bi[64 + lane], b3 = bi[96 + lane];
    float4 o0 = make_float4(a0.x * r0 + b0.x, a0.y * r0 + b0.y, a0.z * r0 + b0.z, a0.w * r0 + b0.w);
    float4 o1 = make_float4(a1.x * r0 + b1.x, a1.y * r0 + b1.y, a1.z * r0 + b1.z, a1.w * r0 + b1.w);
    float4 o2 = make_float4(a2.x * r1 + b2.x, a2.y * r1 + b2.y, a2.z * r1 + b2.z, a2.w * r1 + b2.w);
    float4 o3 = make_float4(a3.x * r1 + b3.x, a3.y * r1 + b3.y, a3.z * r1 + b3.z, a3.w * r1 + b3.w);
    if (ROUND) {
        o0 = make_float4(rtf32(o0.x), rtf32(o0.y), rtf32(o0.z), rtf32(o0.w));
        o1 = make_float4(rtf32(o1.x), rtf32(o1.y), rtf32(o1.z), rtf32(o1.w));
        o2 = make_float4(rtf32(o2.x), rtf32(o2.y), rtf32(o2.z), rtf32(o2.w));
        o3 = make_float4(rtf32(o3.x), rtf32(o3.y), rtf32(o3.z), rtf32(o3.w));
    }
    op[lane] = o0;
    op[32 + lane] = o1;
    op[64 + lane] = o2;
    op[96 + lane] = o3;
}

// ---------------- final head (K12-identical) ----------------
__global__ void __launch_bounds__(512) final_head(
    const float* __restrict__ h,
    const float* __restrict__ bn3g, const float* __restrict__ bn3b,
    const float* __restrict__ bn3m, const float* __restrict__ bn3v,
    const float* __restrict__ w1, const float* __restrict__ b1,
    const float* __restrict__ w2, const float* __restrict__ b2,
    float* __restrict__ out)
{
    int g = blockIdx.x, t = threadIdx.x;
    __shared__ float z[512];
    __shared__ float s1[512];
    int s = g_goff[g], e = g_goff[g + 1];
    float a0 = 0.f, a1 = 0.f, a2 = 0.f, a3 = 0.f;
    int n = s;
    for (; n + 3 < e; n += 4) {
        a0 += h[(size_t)n * D1 + t];
        a1 += h[(size_t)(n + 1) * D1 + t];
        a2 += h[(size_t)(n + 2) * D1 + t];
        a3 += h[(size_t)(n + 3) * D1 + t];
    }
    for (; n < e; n++) a0 += h[(size_t)n * D1 + t];
    float pv = (a0 + a1 + a2 + a3) / fmaxf((float)(e - s), 1.0f);
    float sc = bn3g[t] * rsqrtf(bn3v[t] + 1e-5f);
    z[t] = fmaxf((pv - bn3m[t]) * sc + bn3b[t], 0.f);
    __syncthreads();
    float a = 0.f;
    for (int k = 0; k < 512; k++) a += z[k] * w1[(size_t)k * 512 + t];
    s1[t] = fmaxf(a + b1[t], 0.f);
    __syncthreads();
    if (t < NC * 32) {
        int col = t >> 5, lane = t & 31;
        float sv = 0.f;
        for (int k = lane; k < 512; k += 32) sv += s1[k] * w2[k * NC + col];
#pragma unroll
        for (int o = 16; o; o >>= 1) sv += __shfl_xor_sync(0xffffffffu, sv, o);
        if (!lane) out[g * NC + col] = sv + b2[col];
    }
}

// ---------------- host launcher ----------------
extern "C" void kernel_launch(void* const* d_in, const int* in_sizes, int n_in,
                              void* d_out, int out_size) {
    const float* x        = (const float*)d_in[0];
    const int*   ei       = (const int*)d_in[1];
    const int*   ew       = (const int*)d_in[2];
    const int*   batch    = (const int*)d_in[3];
    const float* mlp_w1   = (const float*)d_in[4];
    const float* mlp_b1   = (const float*)d_in[5];
    const float* bn1_g    = (const float*)d_in[6];
    const float* bn1_b    = (const float*)d_in[7];
    const float* bn1_m    = (const float*)d_in[8];
    const float* bn1_v    = (const float*)d_in[9];
    const float* mlp_w2   = (const float*)d_in[10];
    const float* mlp_b2   = (const float*)d_in[11];
    const float* bn2_g    = (const float*)d_in[12];
    const float* bn2_b    = (const float*)d_in[13];
    const float* bn2_m    = (const float*)d_in[14];
    const float* bn2_v    = (const float*)d_in[15];
    const float* gat0_w   = (const float*)d_in[16];
    const float* gat0_as  = (const float*)d_in[17];
    const float* gat0_ad  = (const float*)d_in[18];
    const float* gat0_bi  = (const float*)d_in[19];
    const float* gat1_w   = (const float*)d_in[20];
    const float* gat1_as  = (const float*)d_in[21];
    const float* gat1_ad  = (const float*)d_in[22];
    const float* gat1_bi  = (const float*)d_in[23];
    const float* bn3_g    = (const float*)d_in[24];
    const float* bn3_b    = (const float*)d_in[25];
    const float* bn3_m    = (const float*)d_in[26];
    const float* bn3_v    = (const float*)d_in[27];
    const float* fin_w1   = (const float*)d_in[28];
    const float* fin_b1   = (const float*)d_in[29];
    const float* fin_w2   = (const float*)d_in[30];
    const float* fin_b2   = (const float*)d_in[31];
    float* out = (float*)d_out;

    float *hp_h1, *hp_h2, *hp_xw, *hp_h3, *hp_h4;
    float *hp_wt0, *hp_wt1, *hp_wt2, *hp_wt3;
    float *hp_sc1, *hp_sh1, *hp_sc2, *hp_sh2;
    float *hp_ls0, *hp_ld0, *hp_ls1, *hp_ld1;
    cudaGetSymbolAddress((void**)&hp_h1, g_h1);
    cudaGetSymbolAddress((void**)&hp_h2, g_h2);
    cudaGetSymbolAddress((void**)&hp_xw, g_xw);
    cudaGetSymbolAddress((void**)&hp_h3, g_h3);
    cudaGetSymbolAddress((void**)&hp_h4, g_h4);
    cudaGetSymbolAddress((void**)&hp_wt0, g_wt0);
    cudaGetSymbolAddress((void**)&hp_wt1, g_wt1);
    cudaGetSymbolAddress((void**)&hp_wt2, g_wt2);
    cudaGetSymbolAddress((void**)&hp_wt3, g_wt3);
    cudaGetSymbolAddress((void**)&hp_sc1, g_sc1);
    cudaGetSymbolAddress((void**)&hp_sh1, g_sh1);
    cudaGetSymbolAddress((void**)&hp_sc2, g_sc2);
    cudaGetSymbolAddress((void**)&hp_sh2, g_sh2);
    cudaGetSymbolAddress((void**)&hp_ls0, g_ls0);
    cudaGetSymbolAddress((void**)&hp_ld0, g_ld0);
    cudaGetSymbolAddress((void**)&hp_ls1, g_ls1);
    cudaGetSymbolAddress((void**)&hp_ld1, g_ld1);

    cudaFuncSetAttribute((const void*)tgemm<1, 1>, cudaFuncAttributeMaxDynamicSharedMemorySize, TG_SMEM);
    cudaFuncSetAttribute((const void*)tgemm<1, 0>, cudaFuncAttributeMaxDynamicSharedMemorySize, TG_SMEM);
    cudaFuncSetAttribute((const void*)tgemm<2, 0>, cudaFuncAttributeMaxDynamicSharedMemorySize, TG_SMEM);

    // one-time stream/event setup (host objects only; graph records node deps)
    static cudaStream_t s2 = nullptr;
    static cudaEvent_t ev1 = nullptr, ev2 = nullptr;
    if (!s2) {
        cudaStreamCreateWithFlags(&s2, cudaStreamNonBlocking);
        cudaEventCreateWithFlags(&ev1, cudaEventDisableTiming);
        cudaEventCreateWithFlags(&ev2, cudaEventDisableTiming);
    }

    // 1) prepass on main stream (produces g_deg, weights, zeros)
    fused_pre<<<NB_ED + NB_TR, 256>>>(batch, ei, ew,
        mlp_b1, bn1_g, bn1_b, bn1_m, bn1_v,
        mlp_b2, bn2_g, bn2_b, bn2_m, bn2_v,
        mlp_w1, mlp_w2, gat0_w, gat1_w);

    // fork: CSR chain on s2, overlapping the two MLP GEMMs
    cudaEventRecord(ev1, 0);
    cudaStreamWaitEvent(s2, ev1, 0);
    scan_blocks<<<(NN + 511) / 512, 512, 0, s2>>>();
    scan_add2<<<(NN + 255) / 256, 256, 0, s2>>>();
    scatter_kernel<<<(EE + 255) / 256, 256, 0, s2>>>(ei, ew);
    cudaEventRecord(ev2, s2);

    const int MB = (NN + 127) / 128;  // 157
    const int AGG_BLOCKS = (NN * 32 + 255) / 256;

    // 2) node MLP on main stream (concurrent with CSR chain)
    tgemm<1, 1><<<dim3(D0 / 64, MB), 256, TG_SMEM>>>(x, hp_wt0, hp_h1, NN, D0, FF,
        hp_sc1, hp_sh1, nullptr, nullptr, nullptr, nullptr);
    tgemm<1, 0><<<dim3(D0 / 64, MB), 256, TG_SMEM>>>(hp_h1, hp_wt1, hp_h2, NN, D0, D0,
        hp_sc2, hp_sh2, nullptr, nullptr, nullptr, nullptr);

    // 3) GAT layer 0
    tgemm<2, 0><<<dim3(D1 / 64, MB), 256, TG_SMEM>>>(hp_h2, hp_wt2, hp_xw, NN, D1, D0,
        nullptr, nullptr, gat0_as, gat0_ad, hp_ls0, hp_ld0);
    cudaStreamWaitEvent(0, ev2, 0);   // join: aggregation needs g_off/g_csr
    gat_agg<1><<<AGG_BLOCKS, 256>>>(hp_xw, gat0_bi, hp_h3, hp_ls0, hp_ld0);

    // 4) GAT layer 1
    tgemm<2, 0><<<dim3(D1 / 64, MB), 256, TG_SMEM>>>(hp_h3, hp_wt3, hp_xw, NN, D1, D1,
        nullptr, nullptr, gat1_as, gat1_ad, hp_ls1, hp_ld1);
    gat_agg<0><<<AGG_BLOCKS, 256>>>(hp_xw, gat1_bi, hp_h4, hp_ls1, hp_ld1);

    // 5) pooled final head
    final_head<<<GG, 512>>>(hp_h4, bn3_g, bn3_b, bn3_m, bn3_v,
                            fin_w1, fin_b1, fin_w2, fin_b2, out);
}